// round 11
// baseline (speedup 1.0000x reference)
#include <cuda_runtime.h>
#include <cuda_fp16.h>
#include <mma.h>
#include <stdint.h>
using namespace nvcuda;

#define Bq   64
#define Ec   8978
#define E2c  4489
#define N1   574592      // B*E   = 64*8978
#define N2   287296      // B*E2  = 64*4489
#define NE1  9193472     // N1*16
#define NE2  4596736     // N2*16
#define SLOPE 0.33f
#define NSL  14          // layer-0 slices per graph
#define SLN  642
#define NSB  896         // 64*14
#define SMQ  (E2c * 16)  // 71824 B dyn smem for quarter-channel staging
#define NBU  17956       // NE2/256

// ---------------- scratch (device globals; no allocations) ----------------
__device__ float    dT1a[N1], dT2a[N1], dT3a[N1];
__device__ float    dX2[N2 * 32];
__device__ float    dT1v[N2 * 32], dT2v[N2 * 32];
__device__ float    dOutB[N2 * 32];
__device__ __half   dX2h[N2 * 32], dT1h[N2 * 32], dT2h[N2 * 32], dT3h[N2 * 32], dX3h[N2 * 32];
__device__ float    dXfPre[N2];
__device__ double   dAcc[128];
__device__ float    dScale[33], dShift[33];
__device__ float    dH1[Bq * 256], dH2[Bq * 128];
__device__ uint16_t dLsrc2[NE2];

// ---------------- init + u16 local src prep (launch 1, every replay) --------
// grid: [0,NBU) src2->u16 ; +64 H1 bias ; +1 dAcc zero ; +1123 dXfPre zero
__global__ void k_init_prep(const int* __restrict__ src2, const float* __restrict__ l1b) {
    int b = blockIdx.x;
    if (b < NBU) {
        int i = b * 256 + threadIdx.x;
        int g = (i >> 4) / E2c;
        dLsrc2[i] = (uint16_t)(src2[i] - g * E2c);
        return;
    }
    b -= NBU;
    if (b < 64) { dH1[b * 256 + threadIdx.x] = l1b[threadIdx.x]; return; }
    b -= 64;
    if (b < 1) { if (threadIdx.x < 128) dAcc[threadIdx.x] = 0.0; return; }
    b -= 1;
    int i = b * 256 + threadIdx.x;
    if (i < N2) dXfPre[i] = 0.f;
}

// ---------------- layer 0: smem-staged scalar matvec, thread-per-node -------
__global__ void __launch_bounds__(256)
k_mv_scalar_s(const float* __restrict__ v, const float* __restrict__ p,
              float* __restrict__ out, const int* __restrict__ src,
              const float* __restrict__ ew,
              float alpha, float beta, float gamma) {
    __shared__ float vs[Ec];
    int b = blockIdx.x;
    int g = b / NSL, s = b - g * NSL;
    int gbase = g * Ec;
    for (int i = threadIdx.x; i < Ec; i += 256) vs[i] = v[gbase + i];
    __syncthreads();
    int start = s * SLN;
    int end = start + SLN; if (end > Ec) end = Ec;
    for (int node = start + threadIdx.x; node < end; node += 256) {
        int gnode = gbase + node;
        const int4*   s4 = (const int4*)(src + (size_t)gnode * 16);
        const float4* w4 = (const float4*)(ew + (size_t)gnode * 16);
        float acc0 = 0.f, acc1 = 0.f;
#pragma unroll
        for (int q = 0; q < 4; q++) {
            int4   ss = __ldg(&s4[q]);
            float4 ww = __ldg(&w4[q]);
            acc0 += ww.x * vs[ss.x - gbase];
            acc1 += ww.y * vs[ss.y - gbase];
            acc0 += ww.z * vs[ss.z - gbase];
            acc1 += ww.w * vs[ss.w - gbase];
        }
        out[gnode] = (alpha * vs[node] + beta * p[gnode] - (acc0 + acc1)) * gamma;
    }
}

// 4 means + 10 second moments of (x, T1, T2, T3) -> dAcc[0..14)
__global__ void k_stats0(const float* __restrict__ x) {
    float loc[14];
#pragma unroll
    for (int i = 0; i < 14; i++) loc[i] = 0.f;
    const float4* X = (const float4*)x;
    const float4* A = (const float4*)dT1a;
    const float4* B = (const float4*)dT2a;
    const float4* C = (const float4*)dT3a;
    int stride = gridDim.x * blockDim.x;
    for (int i = blockIdx.x * blockDim.x + threadIdx.x; i < N1 / 4; i += stride) {
        float4 a = X[i], b = A[i], c = B[i], d = C[i];
        float t0[4] = {a.x, a.y, a.z, a.w};
        float t1[4] = {b.x, b.y, b.z, b.w};
        float t2[4] = {c.x, c.y, c.z, c.w};
        float t3[4] = {d.x, d.y, d.z, d.w};
#pragma unroll
        for (int u = 0; u < 4; u++) {
            loc[0] += t0[u]; loc[1] += t1[u]; loc[2] += t2[u]; loc[3] += t3[u];
            loc[4]  += t0[u] * t0[u]; loc[5]  += t0[u] * t1[u];
            loc[6]  += t0[u] * t2[u]; loc[7]  += t0[u] * t3[u];
            loc[8]  += t1[u] * t1[u]; loc[9]  += t1[u] * t2[u];
            loc[10] += t1[u] * t3[u]; loc[11] += t2[u] * t2[u];
            loc[12] += t2[u] * t3[u]; loc[13] += t3[u] * t3[u];
        }
    }
#pragma unroll
    for (int o = 16; o > 0; o >>= 1)
#pragma unroll
        for (int i = 0; i < 14; i++)
            loc[i] += __shfl_down_sync(0xffffffffu, loc[i], o);
    __shared__ double sh[8][14];
    int w = threadIdx.x >> 5, l = threadIdx.x & 31;
    if (l == 0)
        for (int i = 0; i < 14; i++) sh[w][i] = (double)loc[i];
    __syncthreads();
    if (threadIdx.x == 0) {
        for (int i = 0; i < 14; i++) {
            double s = 0;
            for (int w2 = 0; w2 < 8; w2++) s += sh[w2][i];
            atomicAdd(&dAcc[i], s);
        }
    }
}

__global__ void k_prep0(const float* __restrict__ W0,
                        const float* __restrict__ g0, const float* __restrict__ be0) {
    int c = threadIdx.x;
    if (c >= 32) return;
    double m[4], w[4];
    for (int k = 0; k < 4; k++) { m[k] = dAcc[k] / (double)N1; w[k] = W0[k * 32 + c]; }
    double mean = 0.0;
    for (int k = 0; k < 4; k++) mean += m[k] * w[k];
    const int idx[4][4] = {{4,5,6,7},{5,8,9,10},{6,9,11,12},{7,10,12,13}};
    double var = 0;
    for (int k = 0; k < 4; k++)
        for (int l = 0; l < 4; l++)
            var += w[k] * w[l] * (dAcc[idx[k][l]] / (double)N1 - m[k] * m[l]);
    double sc = (double)g0[c] / sqrt(var + 1e-5);
    dScale[c] = (float)sc;
    dShift[c] = (float)((double)be0[c] - mean * sc);
}

// fused: project T->32ch, BN affine, LeakyReLU, Graclus pair-max pool
__global__ void k_pool(const float* __restrict__ x, const float* __restrict__ W0) {
    int t = blockIdx.x * blockDim.x + threadIdx.x;
    int p = t >> 5;
    if (p >= N2) return;
    int c = t & 31;
    float w0 = W0[c], w1 = W0[32 + c], w2 = W0[64 + c], w3 = W0[96 + c];
    float sc = dScale[c], sh = dShift[c];
    int n0 = 2 * p, n1 = 2 * p + 1;
    float o0 = x[n0] * w0 + dT1a[n0] * w1 + dT2a[n0] * w2 + dT3a[n0] * w3;
    float o1 = x[n1] * w0 + dT1a[n1] * w1 + dT2a[n1] * w2 + dT3a[n1] * w3;
    o0 = o0 * sc + sh; o0 = o0 > 0.f ? o0 : SLOPE * o0;
    o1 = o1 * sc + sh; o1 = o1 > 0.f ? o1 : SLOPE * o1;
    float r = fmaxf(o0, o1);
    dX2[p * 32 + c]  = r;
    dX2h[p * 32 + c] = __float2half(r);
}

// ------- layers 1/2: quarter-channel smem-staged matvec, thread-per-node ----
// block (g,q): stages graph g's channels [q*8, q*8+8) as uint4 rows in smem,
// then each thread does one node: 16 smem gathers of 16B, fp32 accumulate.
__global__ void __launch_bounds__(512, 3)
k_mv_vec_q(const float* __restrict__ vf, const __half* __restrict__ vh,
           const float* __restrict__ pf,
           float* __restrict__ outf, __half* __restrict__ outh,
           const float* __restrict__ ew,
           float alpha, float beta, float gamma, int write_f32) {
    extern __shared__ __align__(16) uint4 vs[];     // [E2c]
    int blk = blockIdx.x;
    int g = blk >> 2, q = blk & 3;
    int gbase = g * E2c;
    const uint4* stg = (const uint4*)(vh + (size_t)gbase * 32 + q * 8);
    for (int i = threadIdx.x; i < E2c; i += 512) vs[i] = stg[(size_t)i * 4];
    __syncthreads();
    for (int n = threadIdx.x; n < E2c; n += 512) {
        int gnode = gbase + n;
        const uint4* sp = (const uint4*)(dLsrc2 + (size_t)gnode * 16);
        uint4 sa = __ldg(&sp[0]);
        uint4 sb = __ldg(&sp[1]);
        uint16_t se[16];
        *(uint4*)&se[0] = sa;
        *(uint4*)&se[8] = sb;
        const float4* wp = (const float4*)(ew + (size_t)gnode * 16);
        float4 w0 = __ldg(&wp[0]), w1 = __ldg(&wp[1]);
        float4 w2 = __ldg(&wp[2]), w3 = __ldg(&wp[3]);
        float we[16] = {w0.x, w0.y, w0.z, w0.w, w1.x, w1.y, w1.z, w1.w,
                        w2.x, w2.y, w2.z, w2.w, w3.x, w3.y, w3.z, w3.w};
        float a0 = 0.f, a1 = 0.f, a2 = 0.f, a3 = 0.f;
        float a4 = 0.f, a5 = 0.f, a6 = 0.f, a7 = 0.f;
#pragma unroll
        for (int e = 0; e < 16; e++) {
            uint4 d = vs[se[e]];
            float w = we[e];
            float2 f;
            f = __half22float2(*(__half2*)&d.x); a0 += w * f.x; a1 += w * f.y;
            f = __half22float2(*(__half2*)&d.y); a2 += w * f.x; a3 += w * f.y;
            f = __half22float2(*(__half2*)&d.z); a4 += w * f.x; a5 += w * f.y;
            f = __half22float2(*(__half2*)&d.w); a6 += w * f.x; a7 += w * f.y;
        }
        size_t o = (size_t)gnode * 32 + q * 8;
        float4 v0 = __ldg((const float4*)(vf + o));
        float4 v1 = __ldg((const float4*)(vf + o + 4));
        float4 p0 = make_float4(0, 0, 0, 0), p1 = p0;
        if (beta != 0.f) {
            p0 = __ldg((const float4*)(pf + o));
            p1 = __ldg((const float4*)(pf + o + 4));
        }
        float r0 = (alpha * v0.x + beta * p0.x - a0) * gamma;
        float r1 = (alpha * v0.y + beta * p0.y - a1) * gamma;
        float r2 = (alpha * v0.z + beta * p0.z - a2) * gamma;
        float r3 = (alpha * v0.w + beta * p0.w - a3) * gamma;
        float r4 = (alpha * v1.x + beta * p1.x - a4) * gamma;
        float r5 = (alpha * v1.y + beta * p1.y - a5) * gamma;
        float r6 = (alpha * v1.z + beta * p1.z - a6) * gamma;
        float r7 = (alpha * v1.w + beta * p1.w - a7) * gamma;
        if (write_f32) {
            *(float4*)(outf + o)     = make_float4(r0, r1, r2, r3);
            *(float4*)(outf + o + 4) = make_float4(r4, r5, r6, r7);
        }
        uint4 ho;
        *(__half2*)&ho.x = __floats2half2_rn(r0, r1);
        *(__half2*)&ho.y = __floats2half2_rn(r2, r3);
        *(__half2*)&ho.z = __floats2half2_rn(r4, r5);
        *(__half2*)&ho.w = __floats2half2_rn(r6, r7);
        *(uint4*)(outh + o) = ho;
    }
}

// layer-2 final pass, quarter-channel: gather T2, form T3, partial 1-ch
// projection over this quarter's 8 channels -> atomicAdd into dXfPre
__global__ void __launch_bounds__(512, 3)
k_mv_out2_q(const float* __restrict__ vf, const __half* __restrict__ vh,
            const float* __restrict__ pf, const float* __restrict__ x3f,
            const float* __restrict__ ew, const float* __restrict__ W2) {
    extern __shared__ __align__(16) uint4 vs[];
    int blk = blockIdx.x;
    int g = blk >> 2, q = blk & 3;
    int gbase = g * E2c;
    const uint4* stg = (const uint4*)(vh + (size_t)gbase * 32 + q * 8);
    for (int i = threadIdx.x; i < E2c; i += 512) vs[i] = stg[(size_t)i * 4];
    __syncthreads();
    for (int n = threadIdx.x; n < E2c; n += 512) {
        int gnode = gbase + n;
        const uint4* sp = (const uint4*)(dLsrc2 + (size_t)gnode * 16);
        uint4 sa = __ldg(&sp[0]);
        uint4 sb = __ldg(&sp[1]);
        uint16_t se[16];
        *(uint4*)&se[0] = sa;
        *(uint4*)&se[8] = sb;
        const float4* wp = (const float4*)(ew + (size_t)gnode * 16);
        float4 w0 = __ldg(&wp[0]), w1 = __ldg(&wp[1]);
        float4 w2 = __ldg(&wp[2]), w3 = __ldg(&wp[3]);
        float we[16] = {w0.x, w0.y, w0.z, w0.w, w1.x, w1.y, w1.z, w1.w,
                        w2.x, w2.y, w2.z, w2.w, w3.x, w3.y, w3.z, w3.w};
        float a0 = 0.f, a1 = 0.f, a2 = 0.f, a3 = 0.f;
        float a4 = 0.f, a5 = 0.f, a6 = 0.f, a7 = 0.f;
#pragma unroll
        for (int e = 0; e < 16; e++) {
            uint4 d = vs[se[e]];
            float w = we[e];
            float2 f;
            f = __half22float2(*(__half2*)&d.x); a0 += w * f.x; a1 += w * f.y;
            f = __half22float2(*(__half2*)&d.y); a2 += w * f.x; a3 += w * f.y;
            f = __half22float2(*(__half2*)&d.z); a4 += w * f.x; a5 += w * f.y;
            f = __half22float2(*(__half2*)&d.w); a6 += w * f.x; a7 += w * f.y;
        }
        size_t o = (size_t)gnode * 32 + q * 8;
        float4 v0 = __ldg((const float4*)(vf + o));     // T2
        float4 v1 = __ldg((const float4*)(vf + o + 4));
        float4 p0 = __ldg((const float4*)(pf + o));     // T1
        float4 p1 = __ldg((const float4*)(pf + o + 4));
        float4 x0 = __ldg((const float4*)(x3f + o));    // layer-2 input
        float4 x1 = __ldg((const float4*)(x3f + o + 4));
        int jc = q * 8;
        float4 u0 = __ldg((const float4*)(W2 + jc));        // W2[0][jc..]
        float4 u1 = __ldg((const float4*)(W2 + jc + 4));
        float4 t0 = __ldg((const float4*)(W2 + 32 + jc));   // W2[1]
        float4 t1 = __ldg((const float4*)(W2 + 32 + jc + 4));
        float4 s0 = __ldg((const float4*)(W2 + 64 + jc));   // W2[2]
        float4 s1 = __ldg((const float4*)(W2 + 64 + jc + 4));
        float4 q0 = __ldg((const float4*)(W2 + 96 + jc));   // W2[3]
        float4 q1 = __ldg((const float4*)(W2 + 96 + jc + 4));
        const float c3 = 1.f / 3.f;
        float t3_0 = (5.f * v0.x - 2.f * p0.x - a0) * c3;
        float t3_1 = (5.f * v0.y - 2.f * p0.y - a1) * c3;
        float t3_2 = (5.f * v0.z - 2.f * p0.z - a2) * c3;
        float t3_3 = (5.f * v0.w - 2.f * p0.w - a3) * c3;
        float t3_4 = (5.f * v1.x - 2.f * p1.x - a4) * c3;
        float t3_5 = (5.f * v1.y - 2.f * p1.y - a5) * c3;
        float t3_6 = (5.f * v1.z - 2.f * p1.z - a6) * c3;
        float t3_7 = (5.f * v1.w - 2.f * p1.w - a7) * c3;
        float pn =
            x0.x * u0.x + x0.y * u0.y + x0.z * u0.z + x0.w * u0.w +
            x1.x * u1.x + x1.y * u1.y + x1.z * u1.z + x1.w * u1.w +
            p0.x * t0.x + p0.y * t0.y + p0.z * t0.z + p0.w * t0.w +
            p1.x * t1.x + p1.y * t1.y + p1.z * t1.z + p1.w * t1.w +
            v0.x * s0.x + v0.y * s0.y + v0.z * s0.z + v0.w * s0.w +
            v1.x * s1.x + v1.y * s1.y + v1.z * s1.z + v1.w * s1.w +
            t3_0 * q0.x + t3_1 * q0.y + t3_2 * q0.z + t3_3 * q0.w +
            t3_4 * q1.x + t3_5 * q1.y + t3_6 * q1.z + t3_7 * q1.w;
        atomicAdd(&dXfPre[gnode], pn);
    }
}

// scalar sum/sumsq over dXfPre -> dAcc[96,97]
__global__ void k_statsF() {
    const float4* a4 = (const float4*)dXfPre;
    int stride = gridDim.x * blockDim.x;
    float s = 0.f, q = 0.f;
    for (int i = blockIdx.x * blockDim.x + threadIdx.x; i < N2 / 4; i += stride) {
        float4 v = a4[i];
        s += v.x + v.y + v.z + v.w;
        q += v.x * v.x + v.y * v.y + v.z * v.z + v.w * v.w;
    }
#pragma unroll
    for (int o = 16; o > 0; o >>= 1) {
        s += __shfl_down_sync(0xffffffffu, s, o);
        q += __shfl_down_sync(0xffffffffu, q, o);
    }
    __shared__ float shs[8], shq[8];
    int w = threadIdx.x >> 5;
    if ((threadIdx.x & 31) == 0) { shs[w] = s; shq[w] = q; }
    __syncthreads();
    if (threadIdx.x == 0) {
        float ts = 0, tq = 0;
        for (int i = 0; i < 8; i++) { ts += shs[i]; tq += shq[i]; }
        atomicAdd(&dAcc[96], (double)ts);
        atomicAdd(&dAcc[97], (double)tq);
    }
}

// out = [A0|A1|A2|A3](fp16) @ W(128x32) split-precision, tensor cores, fused stats
__global__ void __launch_bounds__(256)
k_outgemm_mma(const __half* __restrict__ A0, const __half* __restrict__ A1,
              const __half* __restrict__ A2, const __half* __restrict__ A3,
              const float* __restrict__ W, float* __restrict__ out) {
    __shared__ __half Wh[2][128][40];
    __shared__ float ssum[32], ssq[32];
    int t = threadIdx.x;
    int nb = blockIdx.x * 128;
    if (t < 32) { ssum[t] = 0.f; ssq[t] = 0.f; }
    for (int i = t; i < 4096; i += 256) {
        int k = i >> 5, c = i & 31;
        float w = W[i];
        __half h = __float2half(w);
        Wh[0][k][c] = h;
        Wh[1][k][c] = __float2half(w - __half2float(h));
    }
    __syncthreads();
    int w = t >> 5;
    const __half* Aks[4] = {A0, A1, A2, A3};
    wmma::fragment<wmma::accumulator, 16, 16, 16, float> c0, c1;
    wmma::fill_fragment(c0, 0.f);
    wmma::fill_fragment(c1, 0.f);
#pragma unroll
    for (int k0 = 0; k0 < 8; k0++) {
        const __half* Ak = Aks[k0 >> 1];
        wmma::fragment<wmma::matrix_a, 16, 16, 16, __half, wmma::row_major> a;
        wmma::load_matrix_sync(a, Ak + (size_t)(nb + w * 16) * 32 + (k0 & 1) * 16, 32);
        wmma::fragment<wmma::matrix_b, 16, 16, 16, __half, wmma::row_major> b;
        wmma::load_matrix_sync(b, &Wh[0][k0 * 16][0], 40);
        wmma::mma_sync(c0, a, b, c0);
        wmma::load_matrix_sync(b, &Wh[1][k0 * 16][0], 40);
        wmma::mma_sync(c0, a, b, c0);
        wmma::load_matrix_sync(b, &Wh[0][k0 * 16][16], 40);
        wmma::mma_sync(c1, a, b, c1);
        wmma::load_matrix_sync(b, &Wh[1][k0 * 16][16], 40);
        wmma::mma_sync(c1, a, b, c1);
    }
    __syncthreads();
    float* Cs = (float*)&Wh[0][0][0];     // [128][36]
    wmma::store_matrix_sync(&Cs[(w * 16) * 36], c0, 36, wmma::mem_row_major);
    wmma::store_matrix_sync(&Cs[(w * 16) * 36 + 16], c1, 36, wmma::mem_row_major);
    __syncthreads();
    int c = t & 31, r0 = (t >> 5) * 16;
    float s = 0.f, q = 0.f;
    for (int r = r0; r < r0 + 16; r++) {
        int g = nb + r;
        if (g < N2) {
            float vv = Cs[r * 36 + c];
            s += vv; q += vv * vv;
            out[(size_t)g * 32 + c] = vv;
        }
    }
    atomicAdd(&ssum[c], s);
    atomicAdd(&ssq[c], q);
    __syncthreads();
    if (t < 32) {
        atomicAdd(&dAcc[16 + t], (double)ssum[t]);
        atomicAdd(&dAcc[48 + t], (double)ssq[t]);
    }
}

__global__ void k_prep32(const float* __restrict__ g, const float* __restrict__ be) {
    int c = threadIdx.x;
    if (c >= 32) return;
    double mean = dAcc[16 + c] / (double)N2;
    double var  = dAcc[48 + c] / (double)N2 - mean * mean;
    double sc = (double)g[c] / sqrt(var + 1e-5);
    dScale[c] = (float)sc;
    dShift[c] = (float)((double)be[c] - mean * sc);
}

__global__ void k_apply32(float* __restrict__ a, __half* __restrict__ ah) {
    int i = blockIdx.x * blockDim.x + threadIdx.x;
    float4 v = ((const float4*)a)[i];
    int c = (i & 7) * 4;
    float s0 = dScale[c],     h0 = dShift[c];
    float s1 = dScale[c + 1], h1 = dShift[c + 1];
    float s2 = dScale[c + 2], h2 = dShift[c + 2];
    float s3 = dScale[c + 3], h3 = dShift[c + 3];
    v.x = v.x * s0 + h0; v.x = v.x > 0.f ? v.x : SLOPE * v.x;
    v.y = v.y * s1 + h1; v.y = v.y > 0.f ? v.y : SLOPE * v.y;
    v.z = v.z * s2 + h2; v.z = v.z > 0.f ? v.z : SLOPE * v.z;
    v.w = v.w * s3 + h3; v.w = v.w > 0.f ? v.w : SLOPE * v.w;
    ((float4*)a)[i] = v;
    ((__half2*)ah)[i * 2]     = __floats2half2_rn(v.x, v.y);
    ((__half2*)ah)[i * 2 + 1] = __floats2half2_rn(v.z, v.w);
}

// ---------------- MLP head ----------------
__global__ void k_lin1(const float* __restrict__ W,
                       const float* __restrict__ g2, const float* __restrict__ be2) {
    __shared__ float sm[16 * 128];
    __shared__ float sSc, sSh;
    int c = threadIdx.x;
    if (c == 0) {
        double mean = dAcc[96] / (double)N2;
        double var  = dAcc[97] / (double)N2 - mean * mean;
        double sc = (double)g2[0] / sqrt(var + 1e-5);
        sSc = (float)sc;
        sSh = (float)((double)be2[0] - mean * sc);
    }
    __syncthreads();
    int jbase = blockIdx.x * 128;
    int rbase = blockIdx.y * 16;
    for (int i = c; i < 16 * 128; i += 256) {
        int r = i >> 7, j = i & 127, gj = jbase + j;
        float v = 0.f;
        if (gj < E2c) {
            v = dXfPre[(rbase + r) * E2c + gj] * sSc + sSh;
            v = v > 0.f ? v : SLOPE * v;
        }
        sm[i] = v;
    }
    __syncthreads();
    int jlim = E2c - jbase; if (jlim > 128) jlim = 128;
    float acc[16];
#pragma unroll
    for (int r = 0; r < 16; r++) acc[r] = 0.f;
    for (int j = 0; j < jlim; j++) {
        float w = __ldg(&W[(jbase + j) * 256 + c]);
#pragma unroll
        for (int r = 0; r < 16; r++) acc[r] += sm[r * 128 + j] * w;
    }
#pragma unroll
    for (int r = 0; r < 16; r++)
        atomicAdd(&dH1[(rbase + r) * 256 + c], acc[r]);
}

__global__ void k_bnrelu(float* __restrict__ H, const float* __restrict__ g,
                         const float* __restrict__ be, int C) {
    int c = threadIdx.x;
    if (c >= C) return;
    float s = 0, q = 0;
    for (int r = 0; r < Bq; r++) { float v = H[r * C + c]; s += v; q += v * v; }
    float mean = s / (float)Bq, var = q / (float)Bq - mean * mean;
    float sc = g[c] * rsqrtf(var + 1e-5f);
    float sh = be[c] - mean * sc;
    for (int r = 0; r < Bq; r++) {
        float v = H[r * C + c] * sc + sh;
        H[r * C + c] = fmaxf(v, 0.f);
    }
}

__global__ void k_lin2(const float* __restrict__ H1, const float* __restrict__ W,
                       const float* __restrict__ bias, float* __restrict__ H2) {
    __shared__ float row[256];
    int b = blockIdx.x, t = threadIdx.x;
    row[t] = H1[b * 256 + t];
    __syncthreads();
    if (t < 128) {
        float acc = bias[t];
        for (int j = 0; j < 256; j++)
            acc += row[j] * W[j * 128 + t];
        H2[b * 128 + t] = acc;
    }
}

__global__ void k_lin3(const float* __restrict__ H2, const float* __restrict__ W,
                       const float* __restrict__ bias, float* __restrict__ out) {
    int b = blockIdx.x, t = threadIdx.x;
    float p = H2[b * 128 + t] * W[t];
#pragma unroll
    for (int o = 16; o > 0; o >>= 1)
        p += __shfl_down_sync(0xffffffffu, p, o);
    __shared__ float sh[4];
    if ((t & 31) == 0) sh[t >> 5] = p;
    __syncthreads();
    if (t == 0) out[b] = sh[0] + sh[1] + sh[2] + sh[3] + bias[0];
}

// ---------------- launch ----------------
extern "C" void kernel_launch(void* const* d_in, const int* in_sizes, int n_in,
                              void* d_out, int out_size) {
    const float* x_s  = (const float*)d_in[0];
    const int*   ei1  = (const int*)d_in[1];
    const float* ew1  = (const float*)d_in[2];
    const int*   ei2  = (const int*)d_in[3];
    const float* ew2  = (const float*)d_in[4];
    const float* W0   = (const float*)d_in[5];
    const float* g0   = (const float*)d_in[7];
    const float* be0  = (const float*)d_in[8];
    const float* W1   = (const float*)d_in[9];
    const float* g1   = (const float*)d_in[11];
    const float* be1  = (const float*)d_in[12];
    const float* W2   = (const float*)d_in[13];
    const float* g2   = (const float*)d_in[15];
    const float* be2  = (const float*)d_in[16];
    const float* l1W  = (const float*)d_in[17];
    const float* l1b  = (const float*)d_in[18];
    const float* bn1g = (const float*)d_in[19];
    const float* bn1b = (const float*)d_in[20];
    const float* l2W  = (const float*)d_in[21];
    const float* l2b  = (const float*)d_in[22];
    const float* bn2g = (const float*)d_in[23];
    const float* bn2b = (const float*)d_in[24];
    const float* l3W  = (const float*)d_in[25];
    const float* l3b  = (const float*)d_in[26];

    const int* src1 = ei1;
    const int* src2 = ei2;

    float *pT1a, *pT2a, *pT3a, *pX2, *pT1, *pT2, *pOut, *pH1, *pH2;
    __half *pX2h, *pT1h, *pT2h, *pT3h, *pX3h;
    cudaGetSymbolAddress((void**)&pT1a, dT1a);
    cudaGetSymbolAddress((void**)&pT2a, dT2a);
    cudaGetSymbolAddress((void**)&pT3a, dT3a);
    cudaGetSymbolAddress((void**)&pX2, dX2);
    cudaGetSymbolAddress((void**)&pT1, dT1v);
    cudaGetSymbolAddress((void**)&pT2, dT2v);
    cudaGetSymbolAddress((void**)&pOut, dOutB);
    cudaGetSymbolAddress((void**)&pH1, dH1);
    cudaGetSymbolAddress((void**)&pH2, dH2);
    cudaGetSymbolAddress((void**)&pX2h, dX2h);
    cudaGetSymbolAddress((void**)&pT1h, dT1h);
    cudaGetSymbolAddress((void**)&pT2h, dT2h);
    cudaGetSymbolAddress((void**)&pT3h, dT3h);
    cudaGetSymbolAddress((void**)&pX3h, dX3h);

    cudaFuncSetAttribute(k_mv_vec_q, cudaFuncAttributeMaxDynamicSharedMemorySize, SMQ);
    cudaFuncSetAttribute(k_mv_out2_q, cudaFuncAttributeMaxDynamicSharedMemorySize, SMQ);

    const int NBV = (N2 * 32) / 256;   // 35912

    // ---- init + u16 src prep (launch 1) ----
    k_init_prep<<<NBU + 64 + 1 + 1123, 256>>>(ei2, l1b);

    // ---- layer 0 ----
    k_mv_scalar_s<<<NSB, 256>>>(x_s, x_s, pT1a, src1, ew1, 1.f, 0.f, 1.f);
    k_mv_scalar_s<<<NSB, 256>>>(pT1a, x_s, pT2a, src1, ew1, 3.f, -1.f, 0.5f);
    k_mv_scalar_s<<<NSB, 256>>>(pT2a, pT1a, pT3a, src1, ew1, 5.f, -2.f, 1.f / 3.f);
    k_stats0<<<562, 256>>>(x_s);
    k_prep0<<<1, 32>>>(W0, g0, be0);
    k_pool<<<NBV, 256>>>(x_s, W0);

    // ---- layer 1 (quarter-channel smem-staged) ----
    k_mv_vec_q<<<256, 512, SMQ>>>(pX2, pX2h, pX2, pT1, pT1h, ew2, 1.f, 0.f, 1.f, 1);
    k_mv_vec_q<<<256, 512, SMQ>>>(pT1, pT1h, pX2, pT2, pT2h, ew2, 3.f, -1.f, 0.5f, 1);
    k_mv_vec_q<<<256, 512, SMQ>>>(pT2, pT2h, pT1, pT2, pT3h, ew2, 5.f, -2.f, 1.f / 3.f, 0);
    k_outgemm_mma<<<(N2 + 127) / 128, 256>>>(pX2h, pT1h, pT2h, pT3h, W1, pOut);
    k_prep32<<<1, 32>>>(g1, be1);
    k_apply32<<<(N2 * 8) / 256, 256>>>(pOut, pX3h);

    // ---- layer 2 ----
    k_mv_vec_q<<<256, 512, SMQ>>>(pOut, pX3h, pOut, pT1, pT1h, ew2, 1.f, 0.f, 1.f, 1);
    k_mv_vec_q<<<256, 512, SMQ>>>(pT1, pT1h, pOut, pT2, pT2h, ew2, 3.f, -1.f, 0.5f, 1);
    k_mv_out2_q<<<256, 512, SMQ>>>(pT2, pT2h, pT1, pOut, ew2, W2);
    k_statsF<<<281, 256>>>();

    // ---- MLP head (layer-2 BN fused into lin1) ----
    k_lin1<<<dim3(36, 4), 256>>>(l1W, g2, be2);
    k_bnrelu<<<1, 256>>>(pH1, bn1g, bn1b, 256);
    k_lin2<<<Bq, 256>>>(pH1, l2W, l2b, pH2);
    k_bnrelu<<<1, 128>>>(pH2, bn2g, bn2b, 128);
    k_lin3<<<Bq, 128>>>(pH2, l3W, l3b, (float*)d_out);
}

// round 12
// speedup vs baseline: 1.4534x; 1.4534x over previous
#include <cuda_runtime.h>
#include <cuda_fp16.h>
#include <mma.h>
#include <stdint.h>
using namespace nvcuda;

#define Bq   64
#define Ec   8978
#define E2c  4489
#define N1   574592      // B*E   = 64*8978
#define N2   287296      // B*E2  = 64*4489
#define NE1  9193472     // N1*16
#define NE2  4596736     // N2*16
#define SLOPE 0.33f
#define NSL  14          // layer-0 slices per graph
#define SLN  642
#define NSB  896         // 64*14 -> 6 blocks/SM, one wave

// ---------------- scratch (device globals; no allocations) ----------------
__device__ float    dT1a[N1], dT2a[N1], dT3a[N1];
__device__ float    dX2[N2 * 32];
__device__ float    dT1v[N2 * 32], dT2v[N2 * 32];
__device__ float    dOutB[N2 * 32];
__device__ __half   dX2h[N2 * 32], dT1h[N2 * 32], dT2h[N2 * 32], dT3h[N2 * 32], dX3h[N2 * 32];
__device__ float    dXfPre[N2];
__device__ double   dAcc[128];
__device__ float    dScale[33], dShift[33];
__device__ float    dH1[Bq * 256], dH2[Bq * 128];

// ---------------- init: H1 bias + dAcc zero (launch 1) ----------------
__global__ void k_init(const float* __restrict__ l1b) {
    int b = blockIdx.x;
    if (b < 64) { dH1[b * 256 + threadIdx.x] = l1b[threadIdx.x]; return; }
    if (threadIdx.x < 128) dAcc[threadIdx.x] = 0.0;
}

// ---------------- layer 0: smem-staged scalar matvec, thread-per-node -------
__global__ void __launch_bounds__(256)
k_mv_scalar_s(const float* __restrict__ v, const float* __restrict__ p,
              float* __restrict__ out, const int* __restrict__ src,
              const float* __restrict__ ew,
              float alpha, float beta, float gamma) {
    __shared__ float vs[Ec];
    int b = blockIdx.x;
    int g = b / NSL, s = b - g * NSL;
    int gbase = g * Ec;
    for (int i = threadIdx.x; i < Ec; i += 256) vs[i] = v[gbase + i];
    __syncthreads();
    int start = s * SLN;
    int end = start + SLN; if (end > Ec) end = Ec;
    for (int node = start + threadIdx.x; node < end; node += 256) {
        int gnode = gbase + node;
        const int4*   s4 = (const int4*)(src + (size_t)gnode * 16);
        const float4* w4 = (const float4*)(ew + (size_t)gnode * 16);
        float acc0 = 0.f, acc1 = 0.f;
#pragma unroll
        for (int q = 0; q < 4; q++) {
            int4   ss = __ldg(&s4[q]);
            float4 ww = __ldg(&w4[q]);
            acc0 += ww.x * vs[ss.x - gbase];
            acc1 += ww.y * vs[ss.y - gbase];
            acc0 += ww.z * vs[ss.z - gbase];
            acc1 += ww.w * vs[ss.w - gbase];
        }
        out[gnode] = (alpha * vs[node] + beta * p[gnode] - (acc0 + acc1)) * gamma;
    }
}

// 4 means + 10 second moments of (x, T1, T2, T3) -> dAcc[0..14)
__global__ void k_stats0(const float* __restrict__ x) {
    float loc[14];
#pragma unroll
    for (int i = 0; i < 14; i++) loc[i] = 0.f;
    const float4* X = (const float4*)x;
    const float4* A = (const float4*)dT1a;
    const float4* B = (const float4*)dT2a;
    const float4* C = (const float4*)dT3a;
    int stride = gridDim.x * blockDim.x;
    for (int i = blockIdx.x * blockDim.x + threadIdx.x; i < N1 / 4; i += stride) {
        float4 a = X[i], b = A[i], c = B[i], d = C[i];
        float t0[4] = {a.x, a.y, a.z, a.w};
        float t1[4] = {b.x, b.y, b.z, b.w};
        float t2[4] = {c.x, c.y, c.z, c.w};
        float t3[4] = {d.x, d.y, d.z, d.w};
#pragma unroll
        for (int u = 0; u < 4; u++) {
            loc[0] += t0[u]; loc[1] += t1[u]; loc[2] += t2[u]; loc[3] += t3[u];
            loc[4]  += t0[u] * t0[u]; loc[5]  += t0[u] * t1[u];
            loc[6]  += t0[u] * t2[u]; loc[7]  += t0[u] * t3[u];
            loc[8]  += t1[u] * t1[u]; loc[9]  += t1[u] * t2[u];
            loc[10] += t1[u] * t3[u]; loc[11] += t2[u] * t2[u];
            loc[12] += t2[u] * t3[u]; loc[13] += t3[u] * t3[u];
        }
    }
#pragma unroll
    for (int o = 16; o > 0; o >>= 1)
#pragma unroll
        for (int i = 0; i < 14; i++)
            loc[i] += __shfl_down_sync(0xffffffffu, loc[i], o);
    __shared__ double sh[8][14];
    int w = threadIdx.x >> 5, l = threadIdx.x & 31;
    if (l == 0)
        for (int i = 0; i < 14; i++) sh[w][i] = (double)loc[i];
    __syncthreads();
    if (threadIdx.x == 0) {
        for (int i = 0; i < 14; i++) {
            double s = 0;
            for (int w2 = 0; w2 < 8; w2++) s += sh[w2][i];
            atomicAdd(&dAcc[i], s);
        }
    }
}

__global__ void k_prep0(const float* __restrict__ W0,
                        const float* __restrict__ g0, const float* __restrict__ be0) {
    int c = threadIdx.x;
    if (c >= 32) return;
    double m[4], w[4];
    for (int k = 0; k < 4; k++) { m[k] = dAcc[k] / (double)N1; w[k] = W0[k * 32 + c]; }
    double mean = 0.0;
    for (int k = 0; k < 4; k++) mean += m[k] * w[k];
    const int idx[4][4] = {{4,5,6,7},{5,8,9,10},{6,9,11,12},{7,10,12,13}};
    double var = 0;
    for (int k = 0; k < 4; k++)
        for (int l = 0; l < 4; l++)
            var += w[k] * w[l] * (dAcc[idx[k][l]] / (double)N1 - m[k] * m[l]);
    double sc = (double)g0[c] / sqrt(var + 1e-5);
    dScale[c] = (float)sc;
    dShift[c] = (float)((double)be0[c] - mean * sc);
}

// fused: project T->32ch, BN affine, LeakyReLU, Graclus pair-max pool
__global__ void k_pool(const float* __restrict__ x, const float* __restrict__ W0) {
    int t = blockIdx.x * blockDim.x + threadIdx.x;
    int p = t >> 5;
    if (p >= N2) return;
    int c = t & 31;
    float w0 = W0[c], w1 = W0[32 + c], w2 = W0[64 + c], w3 = W0[96 + c];
    float sc = dScale[c], sh = dShift[c];
    int n0 = 2 * p, n1 = 2 * p + 1;
    float o0 = x[n0] * w0 + dT1a[n0] * w1 + dT2a[n0] * w2 + dT3a[n0] * w3;
    float o1 = x[n1] * w0 + dT1a[n1] * w1 + dT2a[n1] * w2 + dT3a[n1] * w3;
    o0 = o0 * sc + sh; o0 = o0 > 0.f ? o0 : SLOPE * o0;
    o1 = o1 * sc + sh; o1 = o1 > 0.f ? o1 : SLOPE * o1;
    float r = fmaxf(o0, o1);
    dX2[p * 32 + c]  = r;
    dX2h[p * 32 + c] = __float2half(r);
}

// ---------------- layers 1/2: 32-dim matvec + Laguerre combine -------------
// TWO nodes per warp: half-warp per node, lane owns a channel PAIR (half2).
// Same memory sectors as the 1-node version; half the instructions per node.
__global__ void k_mv_vec(const float* __restrict__ v, const __half* __restrict__ vh,
                         const float* __restrict__ p,
                         float* __restrict__ out, __half* __restrict__ outh,
                         const int* __restrict__ src, const float* __restrict__ ew,
                         float alpha, float beta, float gamma, int write_f32) {
    int t = blockIdx.x * blockDim.x + threadIdx.x;
    int warp = t >> 5;
    int lane = t & 31;
    int half = lane >> 4;          // which node of the pair
    int hl   = lane & 15;          // lane within half: edge slot / channel pair
    int node = warp * 2 + half;
    int base = node * 16;
    int   sl = src[base + hl];     // this half's 16 srcs live in its 16 lanes
    float wl = ew[base + hl];
    int sbase = half << 4;
    float accx = 0.f, accy = 0.f;
#pragma unroll
    for (int e = 0; e < 16; e++) {
        int   s  = __shfl_sync(0xffffffffu, sl, sbase + e);
        float wt = __shfl_sync(0xffffffffu, wl, sbase + e);
        __half2 h = __ldg((const __half2*)(vh + (size_t)s * 32) + hl);
        float2 f = __half22float2(h);
        accx += wt * f.x;
        accy += wt * f.y;
    }
    size_t o = (size_t)node * 32 + 2 * hl;
    float2 vv = *(const float2*)(v + o);
    float2 pp = *(const float2*)(p + o);
    float rx = (alpha * vv.x + beta * pp.x - accx) * gamma;
    float ry = (alpha * vv.y + beta * pp.y - accy) * gamma;
    if (write_f32) *(float2*)(out + o) = make_float2(rx, ry);
    *(__half2*)(outh + o) = __floats2half2_rn(rx, ry);
}

// out = [A0|A1|A2|A3](fp16) @ W(128x32) split-precision (Wh+Wl), tensor cores.
// A-fragments loaded straight from global (row-major ldm=32). Fused stats.
__global__ void __launch_bounds__(256)
k_outgemm_mma(const __half* __restrict__ A0, const __half* __restrict__ A1,
              const __half* __restrict__ A2, const __half* __restrict__ A3,
              const float* __restrict__ W, float* __restrict__ out) {
    __shared__ __half Wh[2][128][40];
    __shared__ float ssum[32], ssq[32];
    int t = threadIdx.x;
    int nb = blockIdx.x * 128;
    if (t < 32) { ssum[t] = 0.f; ssq[t] = 0.f; }
    for (int i = t; i < 4096; i += 256) {
        int k = i >> 5, c = i & 31;
        float w = W[i];
        __half h = __float2half(w);
        Wh[0][k][c] = h;
        Wh[1][k][c] = __float2half(w - __half2float(h));
    }
    __syncthreads();
    int w = t >> 5;
    const __half* Aks[4] = {A0, A1, A2, A3};
    wmma::fragment<wmma::accumulator, 16, 16, 16, float> c0, c1;
    wmma::fill_fragment(c0, 0.f);
    wmma::fill_fragment(c1, 0.f);
#pragma unroll
    for (int k0 = 0; k0 < 8; k0++) {
        const __half* Ak = Aks[k0 >> 1];
        wmma::fragment<wmma::matrix_a, 16, 16, 16, __half, wmma::row_major> a;
        wmma::load_matrix_sync(a, Ak + (size_t)(nb + w * 16) * 32 + (k0 & 1) * 16, 32);
        wmma::fragment<wmma::matrix_b, 16, 16, 16, __half, wmma::row_major> b;
        wmma::load_matrix_sync(b, &Wh[0][k0 * 16][0], 40);
        wmma::mma_sync(c0, a, b, c0);
        wmma::load_matrix_sync(b, &Wh[1][k0 * 16][0], 40);
        wmma::mma_sync(c0, a, b, c0);
        wmma::load_matrix_sync(b, &Wh[0][k0 * 16][16], 40);
        wmma::mma_sync(c1, a, b, c1);
        wmma::load_matrix_sync(b, &Wh[1][k0 * 16][16], 40);
        wmma::mma_sync(c1, a, b, c1);
    }
    __syncthreads();
    float* Cs = (float*)&Wh[0][0][0];     // [128][36]
    wmma::store_matrix_sync(&Cs[(w * 16) * 36], c0, 36, wmma::mem_row_major);
    wmma::store_matrix_sync(&Cs[(w * 16) * 36 + 16], c1, 36, wmma::mem_row_major);
    __syncthreads();
    int c = t & 31, r0 = (t >> 5) * 16;
    float s = 0.f, q = 0.f;
    for (int r = r0; r < r0 + 16; r++) {
        int g = nb + r;
        if (g < N2) {
            float vv = Cs[r * 36 + c];
            s += vv; q += vv * vv;
            out[(size_t)g * 32 + c] = vv;
        }
    }
    atomicAdd(&ssum[c], s);
    atomicAdd(&ssq[c], q);
    __syncthreads();
    if (t < 32) {
        atomicAdd(&dAcc[16 + t], (double)ssum[t]);
        atomicAdd(&dAcc[48 + t], (double)ssq[t]);
    }
}

// single block: layer-1 BN scale/shift
__global__ void k_prep32(const float* __restrict__ g, const float* __restrict__ be) {
    int c = threadIdx.x;
    if (c >= 32) return;
    double mean = dAcc[16 + c] / (double)N2;
    double var  = dAcc[48 + c] / (double)N2 - mean * mean;
    double sc = (double)g[c] / sqrt(var + 1e-5);
    dScale[c] = (float)sc;
    dShift[c] = (float)((double)be[c] - mean * sc);
}

// BN affine + LeakyReLU, in place; writes fp16 copy. float4 vectorized.
__global__ void k_apply32(float* __restrict__ a, __half* __restrict__ ah) {
    int i = blockIdx.x * blockDim.x + threadIdx.x;   // over N2*8
    float4 v = ((const float4*)a)[i];
    int c = (i & 7) * 4;
    float s0 = dScale[c],     h0 = dShift[c];
    float s1 = dScale[c + 1], h1 = dShift[c + 1];
    float s2 = dScale[c + 2], h2 = dShift[c + 2];
    float s3 = dScale[c + 3], h3 = dShift[c + 3];
    v.x = v.x * s0 + h0; v.x = v.x > 0.f ? v.x : SLOPE * v.x;
    v.y = v.y * s1 + h1; v.y = v.y > 0.f ? v.y : SLOPE * v.y;
    v.z = v.z * s2 + h2; v.z = v.z > 0.f ? v.z : SLOPE * v.z;
    v.w = v.w * s3 + h3; v.w = v.w > 0.f ? v.w : SLOPE * v.w;
    ((float4*)a)[i] = v;
    ((__half2*)ah)[i * 2]     = __floats2half2_rn(v.x, v.y);
    ((__half2*)ah)[i * 2 + 1] = __floats2half2_rn(v.z, v.w);
}

// layer2 final: T3 combine fused with 1-channel output + scalar BN stats
__global__ void k_mv_out2(const float* __restrict__ v, const __half* __restrict__ vh,
                          const float* __restrict__ p, const float* __restrict__ x3,
                          const int* __restrict__ src, const float* __restrict__ ew,
                          const float* __restrict__ W2) {
    int t = blockIdx.x * blockDim.x + threadIdx.x;
    int node = t >> 5;
    int lane = t & 31;
    int base = node * 16;
    int   sl = src[base + (lane & 15)];
    float wl = ew[base + (lane & 15)];
    float acc = 0.f;
#pragma unroll
    for (int e = 0; e < 16; e++) {
        int   s  = __shfl_sync(0xffffffffu, sl, e);
        float wt = __shfl_sync(0xffffffffu, wl, e);
        acc += wt * __half2float(__ldg(&vh[(size_t)s * 32 + lane]));
    }
    size_t o = (size_t)node * 32 + lane;
    float vv = __ldg(&v[o]), pp = __ldg(&p[o]);
    float T3 = (5.f * vv - 2.f * pp - acc) * (1.f / 3.f);
    float val = __ldg(&x3[o]) * W2[lane] + pp * W2[32 + lane] +
                vv * W2[64 + lane] + T3 * W2[96 + lane];
#pragma unroll
    for (int off = 16; off > 0; off >>= 1)
        val += __shfl_down_sync(0xffffffffu, val, off);
    __shared__ float sh_s[8], sh_q[8];
    int w = threadIdx.x >> 5;
    if (lane == 0) {                 // b2 dropped: BN-invariant
        dXfPre[node] = val;
        sh_s[w] = val;
        sh_q[w] = val * val;
    }
    __syncthreads();
    if (threadIdx.x == 0) {
        float s = 0, q = 0;
        for (int i = 0; i < 8; i++) { s += sh_s[i]; q += sh_q[i]; }
        atomicAdd(&dAcc[96], (double)s);
        atomicAdd(&dAcc[97], (double)q);
    }
}

// ---------------- MLP head ----------------
__global__ void k_lin1(const float* __restrict__ W,
                       const float* __restrict__ g2, const float* __restrict__ be2) {
    __shared__ float sm[16 * 128];
    __shared__ float sSc, sSh;
    int c = threadIdx.x;
    if (c == 0) {
        double mean = dAcc[96] / (double)N2;
        double var  = dAcc[97] / (double)N2 - mean * mean;
        double sc = (double)g2[0] / sqrt(var + 1e-5);
        sSc = (float)sc;
        sSh = (float)((double)be2[0] - mean * sc);
    }
    __syncthreads();
    int jbase = blockIdx.x * 128;
    int rbase = blockIdx.y * 16;
    for (int i = c; i < 16 * 128; i += 256) {
        int r = i >> 7, j = i & 127, gj = jbase + j;
        float v = 0.f;
        if (gj < E2c) {
            v = dXfPre[(rbase + r) * E2c + gj] * sSc + sSh;
            v = v > 0.f ? v : SLOPE * v;
        }
        sm[i] = v;
    }
    __syncthreads();
    int jlim = E2c - jbase; if (jlim > 128) jlim = 128;
    float acc[16];
#pragma unroll
    for (int r = 0; r < 16; r++) acc[r] = 0.f;
    for (int j = 0; j < jlim; j++) {
        float w = __ldg(&W[(jbase + j) * 256 + c]);
#pragma unroll
        for (int r = 0; r < 16; r++) acc[r] += sm[r * 128 + j] * w;
    }
#pragma unroll
    for (int r = 0; r < 16; r++)
        atomicAdd(&dH1[(rbase + r) * 256 + c], acc[r]);
}

__global__ void k_bnrelu(float* __restrict__ H, const float* __restrict__ g,
                         const float* __restrict__ be, int C) {
    int c = threadIdx.x;
    if (c >= C) return;
    float s = 0, q = 0;
    for (int r = 0; r < Bq; r++) { float v = H[r * C + c]; s += v; q += v * v; }
    float mean = s / (float)Bq, var = q / (float)Bq - mean * mean;
    float sc = g[c] * rsqrtf(var + 1e-5f);
    float sh = be[c] - mean * sc;
    for (int r = 0; r < Bq; r++) {
        float v = H[r * C + c] * sc + sh;
        H[r * C + c] = fmaxf(v, 0.f);
    }
}

__global__ void k_lin2(const float* __restrict__ H1, const float* __restrict__ W,
                       const float* __restrict__ bias, float* __restrict__ H2) {
    __shared__ float row[256];
    int b = blockIdx.x, t = threadIdx.x;
    row[t] = H1[b * 256 + t];
    __syncthreads();
    if (t < 128) {
        float acc = bias[t];
        for (int j = 0; j < 256; j++)
            acc += row[j] * W[j * 128 + t];
        H2[b * 128 + t] = acc;
    }
}

__global__ void k_lin3(const float* __restrict__ H2, const float* __restrict__ W,
                       const float* __restrict__ bias, float* __restrict__ out) {
    int b = blockIdx.x, t = threadIdx.x;
    float p = H2[b * 128 + t] * W[t];
#pragma unroll
    for (int o = 16; o > 0; o >>= 1)
        p += __shfl_down_sync(0xffffffffu, p, o);
    __shared__ float sh[4];
    if ((t & 31) == 0) sh[t >> 5] = p;
    __syncthreads();
    if (t == 0) out[b] = sh[0] + sh[1] + sh[2] + sh[3] + bias[0];
}

// ---------------- launch ----------------
extern "C" void kernel_launch(void* const* d_in, const int* in_sizes, int n_in,
                              void* d_out, int out_size) {
    const float* x_s  = (const float*)d_in[0];
    const int*   ei1  = (const int*)d_in[1];
    const float* ew1  = (const float*)d_in[2];
    const int*   ei2  = (const int*)d_in[3];
    const float* ew2  = (const float*)d_in[4];
    const float* W0   = (const float*)d_in[5];
    const float* g0   = (const float*)d_in[7];
    const float* be0  = (const float*)d_in[8];
    const float* W1   = (const float*)d_in[9];
    const float* g1   = (const float*)d_in[11];
    const float* be1  = (const float*)d_in[12];
    const float* W2   = (const float*)d_in[13];
    const float* g2   = (const float*)d_in[15];
    const float* be2  = (const float*)d_in[16];
    const float* l1W  = (const float*)d_in[17];
    const float* l1b  = (const float*)d_in[18];
    const float* bn1g = (const float*)d_in[19];
    const float* bn1b = (const float*)d_in[20];
    const float* l2W  = (const float*)d_in[21];
    const float* l2b  = (const float*)d_in[22];
    const float* bn2g = (const float*)d_in[23];
    const float* bn2b = (const float*)d_in[24];
    const float* l3W  = (const float*)d_in[25];
    const float* l3b  = (const float*)d_in[26];

    const int* src1 = ei1;
    const int* src2 = ei2;

    float *pT1a, *pT2a, *pT3a, *pX2, *pT1, *pT2, *pOut, *pH1, *pH2;
    __half *pX2h, *pT1h, *pT2h, *pT3h, *pX3h;
    cudaGetSymbolAddress((void**)&pT1a, dT1a);
    cudaGetSymbolAddress((void**)&pT2a, dT2a);
    cudaGetSymbolAddress((void**)&pT3a, dT3a);
    cudaGetSymbolAddress((void**)&pX2, dX2);
    cudaGetSymbolAddress((void**)&pT1, dT1v);
    cudaGetSymbolAddress((void**)&pT2, dT2v);
    cudaGetSymbolAddress((void**)&pOut, dOutB);
    cudaGetSymbolAddress((void**)&pH1, dH1);
    cudaGetSymbolAddress((void**)&pH2, dH2);
    cudaGetSymbolAddress((void**)&pX2h, dX2h);
    cudaGetSymbolAddress((void**)&pT1h, dT1h);
    cudaGetSymbolAddress((void**)&pT2h, dT2h);
    cudaGetSymbolAddress((void**)&pT3h, dT3h);
    cudaGetSymbolAddress((void**)&pX3h, dX3h);

    const int NBV  = (N2 * 32) / 256;   // 35912 (warp-per-node kernels)
    const int NBV2 = (N2 * 16) / 256;   // 17956 (2-nodes-per-warp kernels)

    // ---- init (launch 1) ----
    k_init<<<65, 256>>>(l1b);

    // ---- layer 0 ----
    k_mv_scalar_s<<<NSB, 256>>>(x_s, x_s, pT1a, src1, ew1, 1.f, 0.f, 1.f);
    k_mv_scalar_s<<<NSB, 256>>>(pT1a, x_s, pT2a, src1, ew1, 3.f, -1.f, 0.5f);
    k_mv_scalar_s<<<NSB, 256>>>(pT2a, pT1a, pT3a, src1, ew1, 5.f, -2.f, 1.f / 3.f);
    k_stats0<<<562, 256>>>(x_s);
    k_prep0<<<1, 32>>>(W0, g0, be0);
    k_pool<<<NBV, 256>>>(x_s, W0);

    // ---- layer 1 (32ch Laguerre conv, 2 nodes/warp) ----
    k_mv_vec<<<NBV2, 256>>>(pX2, pX2h, pX2, pT1, pT1h, src2, ew2, 1.f, 0.f, 1.f, 1);
    k_mv_vec<<<NBV2, 256>>>(pT1, pT1h, pX2, pT2, pT2h, src2, ew2, 3.f, -1.f, 0.5f, 1);
    k_mv_vec<<<NBV2, 256>>>(pT2, pT2h, pT1, pT2, pT3h, src2, ew2, 5.f, -2.f, 1.f / 3.f, 0);
    k_outgemm_mma<<<(N2 + 127) / 128, 256>>>(pX2h, pT1h, pT2h, pT3h, W1, pOut);
    k_prep32<<<1, 32>>>(g1, be1);
    k_apply32<<<(N2 * 8) / 256, 256>>>(pOut, pX3h);    // in-place -> x3 (+fp16)

    // ---- layer 2 (32ch -> 1ch Laguerre conv, output fused) ----
    k_mv_vec<<<NBV2, 256>>>(pOut, pX3h, pOut, pT1, pT1h, src2, ew2, 1.f, 0.f, 1.f, 1);
    k_mv_vec<<<NBV2, 256>>>(pT1, pT1h, pOut, pT2, pT2h, src2, ew2, 3.f, -1.f, 0.5f, 1);
    k_mv_out2<<<NBV, 256>>>(pT2, pT2h, pT1, pOut, src2, ew2, W2);

    // ---- MLP head (layer-2 BN fused into lin1) ----
    k_lin1<<<dim3(36, 4), 256>>>(l1W, g2, be2);
    k_bnrelu<<<1, 256>>>(pH1, bn1g, bn1b, 256);
    k_lin2<<<Bq, 256>>>(pH1, l2W, l2b, pH2);
    k_bnrelu<<<1, 128>>>(pH2, bn2g, bn2b, 128);
    k_lin3<<<Bq, 128>>>(pH2, l3W, l3b, (float*)d_out);
}

// round 13
// speedup vs baseline: 1.6007x; 1.1014x over previous
#include <cuda_runtime.h>
#include <cuda_fp16.h>
#include <mma.h>
#include <stdint.h>
using namespace nvcuda;

#define Bq   64
#define Ec   8978
#define E2c  4489
#define N1   574592      // B*E   = 64*8978
#define N2   287296      // B*E2  = 64*4489
#define NE1  9193472     // N1*16
#define NE2  4596736     // N2*16
#define SLOPE 0.33f
#define NSL  14          // layer-0 slices per graph
#define SLN  642
#define NSB  896         // 64*14 -> 6 blocks/SM, one wave

// ---------------- scratch (device globals; no allocations) ----------------
__device__ float    dT1a[N1], dT2a[N1], dT3a[N1];
__device__ float    dX2[N2 * 32];
__device__ float    dT1v[N2 * 32], dT2v[N2 * 32];
__device__ float    dOutB[N2 * 32];
__device__ __half   dX2h[N2 * 32], dT1h[N2 * 32], dT2h[N2 * 32], dT3h[N2 * 32], dX3h[N2 * 32];
__device__ float    dXfPre[N2];
__device__ double   dAcc[128];
__device__ float    dScale[33], dShift[33];
__device__ float    dH1[Bq * 256], dH2[Bq * 128];

// ---------------- init: H1 bias + dAcc zero (launch 1) ----------------
__global__ void k_init(const float* __restrict__ l1b) {
    int b = blockIdx.x;
    if (b < 64) { dH1[b * 256 + threadIdx.x] = l1b[threadIdx.x]; return; }
    if (threadIdx.x < 128) dAcc[threadIdx.x] = 0.0;
}

// ---------------- layer 0: smem-staged scalar matvec, thread-per-node -------
__global__ void __launch_bounds__(256)
k_mv_scalar_s(const float* __restrict__ v, const float* __restrict__ p,
              float* __restrict__ out, const int* __restrict__ src,
              const float* __restrict__ ew,
              float alpha, float beta, float gamma) {
    __shared__ float vs[Ec];
    int b = blockIdx.x;
    int g = b / NSL, s = b - g * NSL;
    int gbase = g * Ec;
    for (int i = threadIdx.x; i < Ec; i += 256) vs[i] = v[gbase + i];
    __syncthreads();
    int start = s * SLN;
    int end = start + SLN; if (end > Ec) end = Ec;
    for (int node = start + threadIdx.x; node < end; node += 256) {
        int gnode = gbase + node;
        const int4*   s4 = (const int4*)(src + (size_t)gnode * 16);
        const float4* w4 = (const float4*)(ew + (size_t)gnode * 16);
        float acc0 = 0.f, acc1 = 0.f;
#pragma unroll
        for (int q = 0; q < 4; q++) {
            int4   ss = __ldg(&s4[q]);
            float4 ww = __ldg(&w4[q]);
            acc0 += ww.x * vs[ss.x - gbase];
            acc1 += ww.y * vs[ss.y - gbase];
            acc0 += ww.z * vs[ss.z - gbase];
            acc1 += ww.w * vs[ss.w - gbase];
        }
        out[gnode] = (alpha * vs[node] + beta * p[gnode] - (acc0 + acc1)) * gamma;
    }
}

// 4 means + 10 second moments of (x, T1, T2, T3) -> dAcc[0..14)
__global__ void k_stats0(const float* __restrict__ x) {
    float loc[14];
#pragma unroll
    for (int i = 0; i < 14; i++) loc[i] = 0.f;
    const float4* X = (const float4*)x;
    const float4* A = (const float4*)dT1a;
    const float4* B = (const float4*)dT2a;
    const float4* C = (const float4*)dT3a;
    int stride = gridDim.x * blockDim.x;
    for (int i = blockIdx.x * blockDim.x + threadIdx.x; i < N1 / 4; i += stride) {
        float4 a = X[i], b = A[i], c = B[i], d = C[i];
        float t0[4] = {a.x, a.y, a.z, a.w};
        float t1[4] = {b.x, b.y, b.z, b.w};
        float t2[4] = {c.x, c.y, c.z, c.w};
        float t3[4] = {d.x, d.y, d.z, d.w};
#pragma unroll
        for (int u = 0; u < 4; u++) {
            loc[0] += t0[u]; loc[1] += t1[u]; loc[2] += t2[u]; loc[3] += t3[u];
            loc[4]  += t0[u] * t0[u]; loc[5]  += t0[u] * t1[u];
            loc[6]  += t0[u] * t2[u]; loc[7]  += t0[u] * t3[u];
            loc[8]  += t1[u] * t1[u]; loc[9]  += t1[u] * t2[u];
            loc[10] += t1[u] * t3[u]; loc[11] += t2[u] * t2[u];
            loc[12] += t2[u] * t3[u]; loc[13] += t3[u] * t3[u];
        }
    }
#pragma unroll
    for (int o = 16; o > 0; o >>= 1)
#pragma unroll
        for (int i = 0; i < 14; i++)
            loc[i] += __shfl_down_sync(0xffffffffu, loc[i], o);
    __shared__ double sh[8][14];
    int w = threadIdx.x >> 5, l = threadIdx.x & 31;
    if (l == 0)
        for (int i = 0; i < 14; i++) sh[w][i] = (double)loc[i];
    __syncthreads();
    if (threadIdx.x == 0) {
        for (int i = 0; i < 14; i++) {
            double s = 0;
            for (int w2 = 0; w2 < 8; w2++) s += sh[w2][i];
            atomicAdd(&dAcc[i], s);
        }
    }
}

__global__ void k_prep0(const float* __restrict__ W0,
                        const float* __restrict__ g0, const float* __restrict__ be0) {
    int c = threadIdx.x;
    if (c >= 32) return;
    double m[4], w[4];
    for (int k = 0; k < 4; k++) { m[k] = dAcc[k] / (double)N1; w[k] = W0[k * 32 + c]; }
    double mean = 0.0;
    for (int k = 0; k < 4; k++) mean += m[k] * w[k];
    const int idx[4][4] = {{4,5,6,7},{5,8,9,10},{6,9,11,12},{7,10,12,13}};
    double var = 0;
    for (int k = 0; k < 4; k++)
        for (int l = 0; l < 4; l++)
            var += w[k] * w[l] * (dAcc[idx[k][l]] / (double)N1 - m[k] * m[l]);
    double sc = (double)g0[c] / sqrt(var + 1e-5);
    dScale[c] = (float)sc;
    dShift[c] = (float)((double)be0[c] - mean * sc);
}

// fused: project T->32ch, BN affine, LeakyReLU, Graclus pair-max pool
__global__ void k_pool(const float* __restrict__ x, const float* __restrict__ W0) {
    int t = blockIdx.x * blockDim.x + threadIdx.x;
    int p = t >> 5;
    if (p >= N2) return;
    int c = t & 31;
    float w0 = W0[c], w1 = W0[32 + c], w2 = W0[64 + c], w3 = W0[96 + c];
    float sc = dScale[c], sh = dShift[c];
    int n0 = 2 * p, n1 = 2 * p + 1;
    float o0 = x[n0] * w0 + dT1a[n0] * w1 + dT2a[n0] * w2 + dT3a[n0] * w3;
    float o1 = x[n1] * w0 + dT1a[n1] * w1 + dT2a[n1] * w2 + dT3a[n1] * w3;
    o0 = o0 * sc + sh; o0 = o0 > 0.f ? o0 : SLOPE * o0;
    o1 = o1 * sc + sh; o1 = o1 > 0.f ? o1 : SLOPE * o1;
    float r = fmaxf(o0, o1);
    dX2[p * 32 + c]  = r;
    dX2h[p * 32 + c] = __float2half(r);
}

// ---------------- layers 1/2: 32-dim matvec + Laguerre combine -------------
// TWO nodes per warp: half-warp per node, lane owns a channel PAIR (half2).
__global__ void k_mv_vec(const float* __restrict__ v, const __half* __restrict__ vh,
                         const float* __restrict__ p,
                         float* __restrict__ out, __half* __restrict__ outh,
                         const int* __restrict__ src, const float* __restrict__ ew,
                         float alpha, float beta, float gamma, int write_f32) {
    int t = blockIdx.x * blockDim.x + threadIdx.x;
    int warp = t >> 5;
    int lane = t & 31;
    int half = lane >> 4;
    int hl   = lane & 15;
    int node = warp * 2 + half;
    int base = node * 16;
    int   sl = src[base + hl];
    float wl = ew[base + hl];
    int sbase = half << 4;
    float accx = 0.f, accy = 0.f;
#pragma unroll
    for (int e = 0; e < 16; e++) {
        int   s  = __shfl_sync(0xffffffffu, sl, sbase + e);
        float wt = __shfl_sync(0xffffffffu, wl, sbase + e);
        __half2 h = __ldg((const __half2*)(vh + (size_t)s * 32) + hl);
        float2 f = __half22float2(h);
        accx += wt * f.x;
        accy += wt * f.y;
    }
    size_t o = (size_t)node * 32 + 2 * hl;
    float2 vv = *(const float2*)(v + o);
    float2 pp = *(const float2*)(p + o);
    float rx = (alpha * vv.x + beta * pp.x - accx) * gamma;
    float ry = (alpha * vv.y + beta * pp.y - accy) * gamma;
    if (write_f32) *(float2*)(out + o) = make_float2(rx, ry);
    *(__half2*)(outh + o) = __floats2half2_rn(rx, ry);
}

// out = [A0|A1|A2|A3](fp16) @ W(128x32) split-precision (Wh+Wl), tensor cores.
__global__ void __launch_bounds__(256)
k_outgemm_mma(const __half* __restrict__ A0, const __half* __restrict__ A1,
              const __half* __restrict__ A2, const __half* __restrict__ A3,
              const float* __restrict__ W, float* __restrict__ out) {
    __shared__ __half Wh[2][128][40];
    __shared__ float ssum[32], ssq[32];
    int t = threadIdx.x;
    int nb = blockIdx.x * 128;
    if (t < 32) { ssum[t] = 0.f; ssq[t] = 0.f; }
    for (int i = t; i < 4096; i += 256) {
        int k = i >> 5, c = i & 31;
        float w = W[i];
        __half h = __float2half(w);
        Wh[0][k][c] = h;
        Wh[1][k][c] = __float2half(w - __half2float(h));
    }
    __syncthreads();
    int w = t >> 5;
    const __half* Aks[4] = {A0, A1, A2, A3};
    wmma::fragment<wmma::accumulator, 16, 16, 16, float> c0, c1;
    wmma::fill_fragment(c0, 0.f);
    wmma::fill_fragment(c1, 0.f);
#pragma unroll
    for (int k0 = 0; k0 < 8; k0++) {
        const __half* Ak = Aks[k0 >> 1];
        wmma::fragment<wmma::matrix_a, 16, 16, 16, __half, wmma::row_major> a;
        wmma::load_matrix_sync(a, Ak + (size_t)(nb + w * 16) * 32 + (k0 & 1) * 16, 32);
        wmma::fragment<wmma::matrix_b, 16, 16, 16, __half, wmma::row_major> b;
        wmma::load_matrix_sync(b, &Wh[0][k0 * 16][0], 40);
        wmma::mma_sync(c0, a, b, c0);
        wmma::load_matrix_sync(b, &Wh[1][k0 * 16][0], 40);
        wmma::mma_sync(c0, a, b, c0);
        wmma::load_matrix_sync(b, &Wh[0][k0 * 16][16], 40);
        wmma::mma_sync(c1, a, b, c1);
        wmma::load_matrix_sync(b, &Wh[1][k0 * 16][16], 40);
        wmma::mma_sync(c1, a, b, c1);
    }
    __syncthreads();
    float* Cs = (float*)&Wh[0][0][0];     // [128][36]
    wmma::store_matrix_sync(&Cs[(w * 16) * 36], c0, 36, wmma::mem_row_major);
    wmma::store_matrix_sync(&Cs[(w * 16) * 36 + 16], c1, 36, wmma::mem_row_major);
    __syncthreads();
    int c = t & 31, r0 = (t >> 5) * 16;
    float s = 0.f, q = 0.f;
    for (int r = r0; r < r0 + 16; r++) {
        int g = nb + r;
        if (g < N2) {
            float vv = Cs[r * 36 + c];
            s += vv; q += vv * vv;
            out[(size_t)g * 32 + c] = vv;
        }
    }
    atomicAdd(&ssum[c], s);
    atomicAdd(&ssq[c], q);
    __syncthreads();
    if (t < 32) {
        atomicAdd(&dAcc[16 + t], (double)ssum[t]);
        atomicAdd(&dAcc[48 + t], (double)ssq[t]);
    }
}

// single block: layer-1 BN scale/shift
__global__ void k_prep32(const float* __restrict__ g, const float* __restrict__ be) {
    int c = threadIdx.x;
    if (c >= 32) return;
    double mean = dAcc[16 + c] / (double)N2;
    double var  = dAcc[48 + c] / (double)N2 - mean * mean;
    double sc = (double)g[c] / sqrt(var + 1e-5);
    dScale[c] = (float)sc;
    dShift[c] = (float)((double)be[c] - mean * sc);
}

// BN affine + LeakyReLU, in place; writes fp16 copy. float4 vectorized.
__global__ void k_apply32(float* __restrict__ a, __half* __restrict__ ah) {
    int i = blockIdx.x * blockDim.x + threadIdx.x;   // over N2*8
    float4 v = ((const float4*)a)[i];
    int c = (i & 7) * 4;
    float s0 = dScale[c],     h0 = dShift[c];
    float s1 = dScale[c + 1], h1 = dShift[c + 1];
    float s2 = dScale[c + 2], h2 = dShift[c + 2];
    float s3 = dScale[c + 3], h3 = dShift[c + 3];
    v.x = v.x * s0 + h0; v.x = v.x > 0.f ? v.x : SLOPE * v.x;
    v.y = v.y * s1 + h1; v.y = v.y > 0.f ? v.y : SLOPE * v.y;
    v.z = v.z * s2 + h2; v.z = v.z > 0.f ? v.z : SLOPE * v.z;
    v.w = v.w * s3 + h3; v.w = v.w > 0.f ? v.w : SLOPE * v.w;
    ((float4*)a)[i] = v;
    ((__half2*)ah)[i * 2]     = __floats2half2_rn(v.x, v.y);
    ((__half2*)ah)[i * 2 + 1] = __floats2half2_rn(v.z, v.w);
}

// layer2 final, 2 nodes/warp: gather T2 (half2), form T3 pair, dot with W2
// pairs, width-16 reduce -> dXfPre[node] + scalar BN stats (2 nodes per warp)
__global__ void k_mv_out2(const float* __restrict__ v, const __half* __restrict__ vh,
                          const float* __restrict__ p, const float* __restrict__ x3,
                          const int* __restrict__ src, const float* __restrict__ ew,
                          const float* __restrict__ W2) {
    int t = blockIdx.x * blockDim.x + threadIdx.x;
    int warp = t >> 5;
    int lane = t & 31;
    int half = lane >> 4;
    int hl   = lane & 15;
    int node = warp * 2 + half;
    int base = node * 16;
    int   sl = src[base + hl];
    float wl = ew[base + hl];
    int sbase = half << 4;
    float accx = 0.f, accy = 0.f;
#pragma unroll
    for (int e = 0; e < 16; e++) {
        int   s  = __shfl_sync(0xffffffffu, sl, sbase + e);
        float wt = __shfl_sync(0xffffffffu, wl, sbase + e);
        __half2 h = __ldg((const __half2*)(vh + (size_t)s * 32) + hl);
        float2 f = __half22float2(h);
        accx += wt * f.x;
        accy += wt * f.y;
    }
    size_t o = (size_t)node * 32 + 2 * hl;
    float2 vv = *(const float2*)(v + o);     // T2
    float2 pp = *(const float2*)(p + o);     // T1
    float2 xx = *(const float2*)(x3 + o);    // layer-2 input
    int jc = 2 * hl;
    float2 u0 = *(const float2*)(W2 + jc);        // W2[0]
    float2 u1 = *(const float2*)(W2 + 32 + jc);   // W2[1]
    float2 u2 = *(const float2*)(W2 + 64 + jc);   // W2[2]
    float2 u3 = *(const float2*)(W2 + 96 + jc);   // W2[3]
    const float c3 = 1.f / 3.f;
    float t3x = (5.f * vv.x - 2.f * pp.x - accx) * c3;
    float t3y = (5.f * vv.y - 2.f * pp.y - accy) * c3;
    float val = xx.x * u0.x + xx.y * u0.y + pp.x * u1.x + pp.y * u1.y +
                vv.x * u2.x + vv.y * u2.y + t3x * u3.x + t3y * u3.y;
#pragma unroll
    for (int off = 8; off > 0; off >>= 1)
        val += __shfl_down_sync(0xffffffffu, val, off, 16);
    __shared__ float sh_s[16], sh_q[16];
    int wslot = (threadIdx.x >> 5) * 2 + half;
    if (hl == 0) {                   // b2 dropped: BN-invariant
        dXfPre[node] = val;
        sh_s[wslot] = val;
        sh_q[wslot] = val * val;
    }
    __syncthreads();
    if (threadIdx.x == 0) {
        float s = 0, q = 0;
        for (int i = 0; i < 16; i++) { s += sh_s[i]; q += sh_q[i]; }
        atomicAdd(&dAcc[96], (double)s);
        atomicAdd(&dAcc[97], (double)q);
    }
}

// ---------------- MLP head ----------------
__global__ void k_lin1(const float* __restrict__ W,
                       const float* __restrict__ g2, const float* __restrict__ be2) {
    __shared__ float sm[16 * 128];
    __shared__ float sSc, sSh;
    int c = threadIdx.x;
    if (c == 0) {
        double mean = dAcc[96] / (double)N2;
        double var  = dAcc[97] / (double)N2 - mean * mean;
        double sc = (double)g2[0] / sqrt(var + 1e-5);
        sSc = (float)sc;
        sSh = (float)((double)be2[0] - mean * sc);
    }
    __syncthreads();
    int jbase = blockIdx.x * 128;
    int rbase = blockIdx.y * 16;
    for (int i = c; i < 16 * 128; i += 256) {
        int r = i >> 7, j = i & 127, gj = jbase + j;
        float v = 0.f;
        if (gj < E2c) {
            v = dXfPre[(rbase + r) * E2c + gj] * sSc + sSh;
            v = v > 0.f ? v : SLOPE * v;
        }
        sm[i] = v;
    }
    __syncthreads();
    int jlim = E2c - jbase; if (jlim > 128) jlim = 128;
    float acc[16];
#pragma unroll
    for (int r = 0; r < 16; r++) acc[r] = 0.f;
    for (int j = 0; j < jlim; j++) {
        float w = __ldg(&W[(jbase + j) * 256 + c]);
#pragma unroll
        for (int r = 0; r < 16; r++) acc[r] += sm[r * 128 + j] * w;
    }
#pragma unroll
    for (int r = 0; r < 16; r++)
        atomicAdd(&dH1[(rbase + r) * 256 + c], acc[r]);
}

__global__ void k_bnrelu(float* __restrict__ H, const float* __restrict__ g,
                         const float* __restrict__ be, int C) {
    int c = threadIdx.x;
    if (c >= C) return;
    float s = 0, q = 0;
    for (int r = 0; r < Bq; r++) { float v = H[r * C + c]; s += v; q += v * v; }
    float mean = s / (float)Bq, var = q / (float)Bq - mean * mean;
    float sc = g[c] * rsqrtf(var + 1e-5f);
    float sh = be[c] - mean * sc;
    for (int r = 0; r < Bq; r++) {
        float v = H[r * C + c] * sc + sh;
        H[r * C + c] = fmaxf(v, 0.f);
    }
}

__global__ void k_lin2(const float* __restrict__ H1, const float* __restrict__ W,
                       const float* __restrict__ bias, float* __restrict__ H2) {
    __shared__ float row[256];
    int b = blockIdx.x, t = threadIdx.x;
    row[t] = H1[b * 256 + t];
    __syncthreads();
    if (t < 128) {
        float acc = bias[t];
        for (int j = 0; j < 256; j++)
            acc += row[j] * W[j * 128 + t];
        H2[b * 128 + t] = acc;
    }
}

__global__ void k_lin3(const float* __restrict__ H2, const float* __restrict__ W,
                       const float* __restrict__ bias, float* __restrict__ out) {
    int b = blockIdx.x, t = threadIdx.x;
    float p = H2[b * 128 + t] * W[t];
#pragma unroll
    for (int o = 16; o > 0; o >>= 1)
        p += __shfl_down_sync(0xffffffffu, p, o);
    __shared__ float sh[4];
    if ((t & 31) == 0) sh[t >> 5] = p;
    __syncthreads();
    if (t == 0) out[b] = sh[0] + sh[1] + sh[2] + sh[3] + bias[0];
}

// ---------------- launch ----------------
extern "C" void kernel_launch(void* const* d_in, const int* in_sizes, int n_in,
                              void* d_out, int out_size) {
    const float* x_s  = (const float*)d_in[0];
    const int*   ei1  = (const int*)d_in[1];
    const float* ew1  = (const float*)d_in[2];
    const int*   ei2  = (const int*)d_in[3];
    const float* ew2  = (const float*)d_in[4];
    const float* W0   = (const float*)d_in[5];
    const float* g0   = (const float*)d_in[7];
    const float* be0  = (const float*)d_in[8];
    const float* W1   = (const float*)d_in[9];
    const float* g1   = (const float*)d_in[11];
    const float* be1  = (const float*)d_in[12];
    const float* W2   = (const float*)d_in[13];
    const float* g2   = (const float*)d_in[15];
    const float* be2  = (const float*)d_in[16];
    const float* l1W  = (const float*)d_in[17];
    const float* l1b  = (const float*)d_in[18];
    const float* bn1g = (const float*)d_in[19];
    const float* bn1b = (const float*)d_in[20];
    const float* l2W  = (const float*)d_in[21];
    const float* l2b  = (const float*)d_in[22];
    const float* bn2g = (const float*)d_in[23];
    const float* bn2b = (const float*)d_in[24];
    const float* l3W  = (const float*)d_in[25];
    const float* l3b  = (const float*)d_in[26];

    const int* src1 = ei1;
    const int* src2 = ei2;

    float *pT1a, *pT2a, *pT3a, *pX2, *pT1, *pT2, *pOut, *pH1, *pH2;
    __half *pX2h, *pT1h, *pT2h, *pT3h, *pX3h;
    cudaGetSymbolAddress((void**)&pT1a, dT1a);
    cudaGetSymbolAddress((void**)&pT2a, dT2a);
    cudaGetSymbolAddress((void**)&pT3a, dT3a);
    cudaGetSymbolAddress((void**)&pX2, dX2);
    cudaGetSymbolAddress((void**)&pT1, dT1v);
    cudaGetSymbolAddress((void**)&pT2, dT2v);
    cudaGetSymbolAddress((void**)&pOut, dOutB);
    cudaGetSymbolAddress((void**)&pH1, dH1);
    cudaGetSymbolAddress((void**)&pH2, dH2);
    cudaGetSymbolAddress((void**)&pX2h, dX2h);
    cudaGetSymbolAddress((void**)&pT1h, dT1h);
    cudaGetSymbolAddress((void**)&pT2h, dT2h);
    cudaGetSymbolAddress((void**)&pT3h, dT3h);
    cudaGetSymbolAddress((void**)&pX3h, dX3h);

    const int NBV  = (N2 * 32) / 256;   // 35912
    const int NBV2 = (N2 * 16) / 256;   // 17956 (2-nodes-per-warp kernels)

    // ---- init (launch 1) ----
    k_init<<<65, 256>>>(l1b);

    // ---- layer 0 ----
    k_mv_scalar_s<<<NSB, 256>>>(x_s, x_s, pT1a, src1, ew1, 1.f, 0.f, 1.f);
    k_mv_scalar_s<<<NSB, 256>>>(pT1a, x_s, pT2a, src1, ew1, 3.f, -1.f, 0.5f);
    k_mv_scalar_s<<<NSB, 256>>>(pT2a, pT1a, pT3a, src1, ew1, 5.f, -2.f, 1.f / 3.f);
    k_stats0<<<562, 256>>>(x_s);
    k_prep0<<<1, 32>>>(W0, g0, be0);
    k_pool<<<NBV, 256>>>(x_s, W0);

    // ---- layer 1 (32ch Laguerre conv, 2 nodes/warp) ----
    k_mv_vec<<<NBV2, 256>>>(pX2, pX2h, pX2, pT1, pT1h, src2, ew2, 1.f, 0.f, 1.f, 1);
    k_mv_vec<<<NBV2, 256>>>(pT1, pT1h, pX2, pT2, pT2h, src2, ew2, 3.f, -1.f, 0.5f, 1);
    k_mv_vec<<<NBV2, 256>>>(pT2, pT2h, pT1, pT2, pT3h, src2, ew2, 5.f, -2.f, 1.f / 3.f, 0);
    k_outgemm_mma<<<(N2 + 127) / 128, 256>>>(pX2h, pT1h, pT2h, pT3h, W1, pOut);
    k_prep32<<<1, 32>>>(g1, be1);
    k_apply32<<<(N2 * 8) / 256, 256>>>(pOut, pX3h);    // in-place -> x3 (+fp16)

    // ---- layer 2 (32ch -> 1ch Laguerre conv, output fused, 2 nodes/warp) ----
    k_mv_vec<<<NBV2, 256>>>(pOut, pX3h, pOut, pT1, pT1h, src2, ew2, 1.f, 0.f, 1.f, 1);
    k_mv_vec<<<NBV2, 256>>>(pT1, pT1h, pOut, pT2, pT2h, src2, ew2, 3.f, -1.f, 0.5f, 1);
    k_mv_out2<<<NBV2, 256>>>(pT2, pT2h, pT1, pOut, src2, ew2, W2);

    // ---- MLP head (layer-2 BN fused into lin1) ----
    k_lin1<<<dim3(36, 4), 256>>>(l1W, g2, be2);
    k_bnrelu<<<1, 256>>>(pH1, bn1g, bn1b, 256);
    k_lin2<<<Bq, 256>>>(pH1, l2W, l2b, pH2);
    k_bnrelu<<<1, 128>>>(pH2, bn2g, bn2b, 128);
    k_lin3<<<Bq, 128>>>(pH2, l3W, l3b, (float*)d_out);
}

// round 14
// speedup vs baseline: 1.7232x; 1.0765x over previous
#include <cuda_runtime.h>
#include <cuda_fp16.h>
#include <mma.h>
#include <stdint.h>
using namespace nvcuda;

#define Bq   64
#define Ec   8978
#define E2c  4489
#define N1   574592      // B*E   = 64*8978
#define N2   287296      // B*E2  = 64*4489
#define NE1  9193472     // N1*16
#define NE2  4596736     // N2*16
#define SLOPE 0.33f
#define NSL  14          // layer-0 slices per graph
#define SLN  642
#define NSB  896         // 64*14 -> 6 blocks/SM, one wave

// ---------------- scratch (device globals; no allocations) ----------------
__device__ float    dT1a[N1], dT2a[N1], dT3a[N1];
__device__ float    dX2[N2 * 32];
__device__ float    dT1v[N2 * 32], dT2v[N2 * 32];
__device__ float    dOutB[N2 * 32];
__device__ __half   dX2h[N2 * 32], dT1h[N2 * 32], dT2h[N2 * 32], dT3h[N2 * 32], dX3h[N2 * 32];
__device__ float    dXfPre[N2];
__device__ double   dAcc[128];
__device__ float    dScale[33], dShift[33];
__device__ float    dH1[Bq * 256], dH2[Bq * 128];

// ---------------- init: H1 bias + dAcc zero (launch 1) ----------------
__global__ void k_init(const float* __restrict__ l1b) {
    int b = blockIdx.x;
    if (b < 64) { dH1[b * 256 + threadIdx.x] = l1b[threadIdx.x]; return; }
    if (threadIdx.x < 128) dAcc[threadIdx.x] = 0.0;
}

// ---------------- layer 0: smem-staged scalar matvec, thread-per-node -------
__global__ void __launch_bounds__(256)
k_mv_scalar_s(const float* __restrict__ v, const float* __restrict__ p,
              float* __restrict__ out, const int* __restrict__ src,
              const float* __restrict__ ew,
              float alpha, float beta, float gamma) {
    __shared__ float vs[Ec];
    int b = blockIdx.x;
    int g = b / NSL, s = b - g * NSL;
    int gbase = g * Ec;
    for (int i = threadIdx.x; i < Ec; i += 256) vs[i] = v[gbase + i];
    __syncthreads();
    int start = s * SLN;
    int end = start + SLN; if (end > Ec) end = Ec;
    for (int node = start + threadIdx.x; node < end; node += 256) {
        int gnode = gbase + node;
        const int4*   s4 = (const int4*)(src + (size_t)gnode * 16);
        const float4* w4 = (const float4*)(ew + (size_t)gnode * 16);
        float acc0 = 0.f, acc1 = 0.f;
#pragma unroll
        for (int q = 0; q < 4; q++) {
            int4   ss = __ldg(&s4[q]);
            float4 ww = __ldg(&w4[q]);
            acc0 += ww.x * vs[ss.x - gbase];
            acc1 += ww.y * vs[ss.y - gbase];
            acc0 += ww.z * vs[ss.z - gbase];
            acc1 += ww.w * vs[ss.w - gbase];
        }
        out[gnode] = (alpha * vs[node] + beta * p[gnode] - (acc0 + acc1)) * gamma;
    }
}

// 4 means + 10 second moments of (x, T1, T2, T3) -> dAcc[0..14)
__global__ void k_stats0(const float* __restrict__ x) {
    float loc[14];
#pragma unroll
    for (int i = 0; i < 14; i++) loc[i] = 0.f;
    const float4* X = (const float4*)x;
    const float4* A = (const float4*)dT1a;
    const float4* B = (const float4*)dT2a;
    const float4* C = (const float4*)dT3a;
    int stride = gridDim.x * blockDim.x;
    for (int i = blockIdx.x * blockDim.x + threadIdx.x; i < N1 / 4; i += stride) {
        float4 a = X[i], b = A[i], c = B[i], d = C[i];
        float t0[4] = {a.x, a.y, a.z, a.w};
        float t1[4] = {b.x, b.y, b.z, b.w};
        float t2[4] = {c.x, c.y, c.z, c.w};
        float t3[4] = {d.x, d.y, d.z, d.w};
#pragma unroll
        for (int u = 0; u < 4; u++) {
            loc[0] += t0[u]; loc[1] += t1[u]; loc[2] += t2[u]; loc[3] += t3[u];
            loc[4]  += t0[u] * t0[u]; loc[5]  += t0[u] * t1[u];
            loc[6]  += t0[u] * t2[u]; loc[7]  += t0[u] * t3[u];
            loc[8]  += t1[u] * t1[u]; loc[9]  += t1[u] * t2[u];
            loc[10] += t1[u] * t3[u]; loc[11] += t2[u] * t2[u];
            loc[12] += t2[u] * t3[u]; loc[13] += t3[u] * t3[u];
        }
    }
#pragma unroll
    for (int o = 16; o > 0; o >>= 1)
#pragma unroll
        for (int i = 0; i < 14; i++)
            loc[i] += __shfl_down_sync(0xffffffffu, loc[i], o);
    __shared__ double sh[8][14];
    int w = threadIdx.x >> 5, l = threadIdx.x & 31;
    if (l == 0)
        for (int i = 0; i < 14; i++) sh[w][i] = (double)loc[i];
    __syncthreads();
    if (threadIdx.x == 0) {
        for (int i = 0; i < 14; i++) {
            double s = 0;
            for (int w2 = 0; w2 < 8; w2++) s += sh[w2][i];
            atomicAdd(&dAcc[i], s);
        }
    }
}

__global__ void k_prep0(const float* __restrict__ W0,
                        const float* __restrict__ g0, const float* __restrict__ be0) {
    int c = threadIdx.x;
    if (c >= 32) return;
    double m[4], w[4];
    for (int k = 0; k < 4; k++) { m[k] = dAcc[k] / (double)N1; w[k] = W0[k * 32 + c]; }
    double mean = 0.0;
    for (int k = 0; k < 4; k++) mean += m[k] * w[k];
    const int idx[4][4] = {{4,5,6,7},{5,8,9,10},{6,9,11,12},{7,10,12,13}};
    double var = 0;
    for (int k = 0; k < 4; k++)
        for (int l = 0; l < 4; l++)
            var += w[k] * w[l] * (dAcc[idx[k][l]] / (double)N1 - m[k] * m[l]);
    double sc = (double)g0[c] / sqrt(var + 1e-5);
    dScale[c] = (float)sc;
    dShift[c] = (float)((double)be0[c] - mean * sc);
}

// fused: project T->32ch, BN affine, LeakyReLU, Graclus pair-max pool
__global__ void k_pool(const float* __restrict__ x, const float* __restrict__ W0) {
    int t = blockIdx.x * blockDim.x + threadIdx.x;
    int p = t >> 5;
    if (p >= N2) return;
    int c = t & 31;
    float w0 = W0[c], w1 = W0[32 + c], w2 = W0[64 + c], w3 = W0[96 + c];
    float sc = dScale[c], sh = dShift[c];
    int n0 = 2 * p, n1 = 2 * p + 1;
    float o0 = x[n0] * w0 + dT1a[n0] * w1 + dT2a[n0] * w2 + dT3a[n0] * w3;
    float o1 = x[n1] * w0 + dT1a[n1] * w1 + dT2a[n1] * w2 + dT3a[n1] * w3;
    o0 = o0 * sc + sh; o0 = o0 > 0.f ? o0 : SLOPE * o0;
    o1 = o1 * sc + sh; o1 = o1 > 0.f ? o1 : SLOPE * o1;
    float r = fmaxf(o0, o1);
    dX2[p * 32 + c]  = r;
    dX2h[p * 32 + c] = __float2half(r);
}

// ---------------- layers 1/2: 32-dim matvec + Laguerre combine -------------
// FOUR nodes per warp: 8 lanes per node, lane owns 4 channels (uint2 gather).
__global__ void k_mv_vec(const float* __restrict__ v, const __half* __restrict__ vh,
                         const float* __restrict__ p,
                         float* __restrict__ out, __half* __restrict__ outh,
                         const int* __restrict__ src, const float* __restrict__ ew,
                         float alpha, float beta, float gamma, int write_f32) {
    int t = blockIdx.x * blockDim.x + threadIdx.x;
    int warp = t >> 5;
    int lane = t & 31;
    int qtr = lane >> 3;           // which node of the four
    int hl  = lane & 7;            // lane within node: channel quad / edge slot
    int node = warp * 4 + qtr;
    int base = node * 16;
    int   sl0 = src[base + hl];
    int   sl1 = src[base + 8 + hl];
    float wl0 = ew[base + hl];
    float wl1 = ew[base + 8 + hl];
    int qb = qtr << 3;
    float a0 = 0.f, a1 = 0.f, a2 = 0.f, a3 = 0.f;
#pragma unroll
    for (int e = 0; e < 8; e++) {
        int   s  = __shfl_sync(0xffffffffu, sl0, qb + e);
        float wt = __shfl_sync(0xffffffffu, wl0, qb + e);
        uint2 d = __ldg((const uint2*)(vh + (size_t)s * 32) + hl);
        float2 f0 = __half22float2(*(__half2*)&d.x);
        float2 f1 = __half22float2(*(__half2*)&d.y);
        a0 += wt * f0.x; a1 += wt * f0.y; a2 += wt * f1.x; a3 += wt * f1.y;
    }
#pragma unroll
    for (int e = 0; e < 8; e++) {
        int   s  = __shfl_sync(0xffffffffu, sl1, qb + e);
        float wt = __shfl_sync(0xffffffffu, wl1, qb + e);
        uint2 d = __ldg((const uint2*)(vh + (size_t)s * 32) + hl);
        float2 f0 = __half22float2(*(__half2*)&d.x);
        float2 f1 = __half22float2(*(__half2*)&d.y);
        a0 += wt * f0.x; a1 += wt * f0.y; a2 += wt * f1.x; a3 += wt * f1.y;
    }
    size_t o = (size_t)node * 32 + 4 * hl;
    float4 vv = *(const float4*)(v + o);
    float4 pp = *(const float4*)(p + o);
    float r0 = (alpha * vv.x + beta * pp.x - a0) * gamma;
    float r1 = (alpha * vv.y + beta * pp.y - a1) * gamma;
    float r2 = (alpha * vv.z + beta * pp.z - a2) * gamma;
    float r3 = (alpha * vv.w + beta * pp.w - a3) * gamma;
    if (write_f32) *(float4*)(out + o) = make_float4(r0, r1, r2, r3);
    uint2 ho;
    *(__half2*)&ho.x = __floats2half2_rn(r0, r1);
    *(__half2*)&ho.y = __floats2half2_rn(r2, r3);
    *(uint2*)(outh + o) = ho;
}

// out = [A0|A1|A2|A3](fp16) @ W(128x32) split-precision (Wh+Wl), tensor cores.
__global__ void __launch_bounds__(256)
k_outgemm_mma(const __half* __restrict__ A0, const __half* __restrict__ A1,
              const __half* __restrict__ A2, const __half* __restrict__ A3,
              const float* __restrict__ W, float* __restrict__ out) {
    __shared__ __half Wh[2][128][40];
    __shared__ float ssum[32], ssq[32];
    int t = threadIdx.x;
    int nb = blockIdx.x * 128;
    if (t < 32) { ssum[t] = 0.f; ssq[t] = 0.f; }
    for (int i = t; i < 4096; i += 256) {
        int k = i >> 5, c = i & 31;
        float w = W[i];
        __half h = __float2half(w);
        Wh[0][k][c] = h;
        Wh[1][k][c] = __float2half(w - __half2float(h));
    }
    __syncthreads();
    int w = t >> 5;
    const __half* Aks[4] = {A0, A1, A2, A3};
    wmma::fragment<wmma::accumulator, 16, 16, 16, float> c0, c1;
    wmma::fill_fragment(c0, 0.f);
    wmma::fill_fragment(c1, 0.f);
#pragma unroll
    for (int k0 = 0; k0 < 8; k0++) {
        const __half* Ak = Aks[k0 >> 1];
        wmma::fragment<wmma::matrix_a, 16, 16, 16, __half, wmma::row_major> a;
        wmma::load_matrix_sync(a, Ak + (size_t)(nb + w * 16) * 32 + (k0 & 1) * 16, 32);
        wmma::fragment<wmma::matrix_b, 16, 16, 16, __half, wmma::row_major> b;
        wmma::load_matrix_sync(b, &Wh[0][k0 * 16][0], 40);
        wmma::mma_sync(c0, a, b, c0);
        wmma::load_matrix_sync(b, &Wh[1][k0 * 16][0], 40);
        wmma::mma_sync(c0, a, b, c0);
        wmma::load_matrix_sync(b, &Wh[0][k0 * 16][16], 40);
        wmma::mma_sync(c1, a, b, c1);
        wmma::load_matrix_sync(b, &Wh[1][k0 * 16][16], 40);
        wmma::mma_sync(c1, a, b, c1);
    }
    __syncthreads();
    float* Cs = (float*)&Wh[0][0][0];     // [128][36]
    wmma::store_matrix_sync(&Cs[(w * 16) * 36], c0, 36, wmma::mem_row_major);
    wmma::store_matrix_sync(&Cs[(w * 16) * 36 + 16], c1, 36, wmma::mem_row_major);
    __syncthreads();
    int c = t & 31, r0 = (t >> 5) * 16;
    float s = 0.f, q = 0.f;
    for (int r = r0; r < r0 + 16; r++) {
        int g = nb + r;
        if (g < N2) {
            float vv = Cs[r * 36 + c];
            s += vv; q += vv * vv;
            out[(size_t)g * 32 + c] = vv;
        }
    }
    atomicAdd(&ssum[c], s);
    atomicAdd(&ssq[c], q);
    __syncthreads();
    if (t < 32) {
        atomicAdd(&dAcc[16 + t], (double)ssum[t]);
        atomicAdd(&dAcc[48 + t], (double)ssq[t]);
    }
}

// single block: layer-1 BN scale/shift
__global__ void k_prep32(const float* __restrict__ g, const float* __restrict__ be) {
    int c = threadIdx.x;
    if (c >= 32) return;
    double mean = dAcc[16 + c] / (double)N2;
    double var  = dAcc[48 + c] / (double)N2 - mean * mean;
    double sc = (double)g[c] / sqrt(var + 1e-5);
    dScale[c] = (float)sc;
    dShift[c] = (float)((double)be[c] - mean * sc);
}

// BN affine + LeakyReLU, in place; writes fp16 copy. float4 vectorized.
__global__ void k_apply32(float* __restrict__ a, __half* __restrict__ ah) {
    int i = blockIdx.x * blockDim.x + threadIdx.x;   // over N2*8
    float4 v = ((const float4*)a)[i];
    int c = (i & 7) * 4;
    float s0 = dScale[c],     h0 = dShift[c];
    float s1 = dScale[c + 1], h1 = dShift[c + 1];
    float s2 = dScale[c + 2], h2 = dShift[c + 2];
    float s3 = dScale[c + 3], h3 = dShift[c + 3];
    v.x = v.x * s0 + h0; v.x = v.x > 0.f ? v.x : SLOPE * v.x;
    v.y = v.y * s1 + h1; v.y = v.y > 0.f ? v.y : SLOPE * v.y;
    v.z = v.z * s2 + h2; v.z = v.z > 0.f ? v.z : SLOPE * v.z;
    v.w = v.w * s3 + h3; v.w = v.w > 0.f ? v.w : SLOPE * v.w;
    ((float4*)a)[i] = v;
    ((__half2*)ah)[i * 2]     = __floats2half2_rn(v.x, v.y);
    ((__half2*)ah)[i * 2 + 1] = __floats2half2_rn(v.z, v.w);
}

// layer2 final, 4 nodes/warp: gather T2 (uint2), form T3 quad, dot with W2
// quads, width-8 reduce -> dXfPre[node] + scalar BN stats (4 nodes per warp)
__global__ void k_mv_out2(const float* __restrict__ v, const __half* __restrict__ vh,
                          const float* __restrict__ p, const float* __restrict__ x3,
                          const int* __restrict__ src, const float* __restrict__ ew,
                          const float* __restrict__ W2) {
    int t = blockIdx.x * blockDim.x + threadIdx.x;
    int warp = t >> 5;
    int lane = t & 31;
    int qtr = lane >> 3;
    int hl  = lane & 7;
    int node = warp * 4 + qtr;
    int base = node * 16;
    int   sl0 = src[base + hl];
    int   sl1 = src[base + 8 + hl];
    float wl0 = ew[base + hl];
    float wl1 = ew[base + 8 + hl];
    int qb = qtr << 3;
    float a0 = 0.f, a1 = 0.f, a2 = 0.f, a3 = 0.f;
#pragma unroll
    for (int e = 0; e < 8; e++) {
        int   s  = __shfl_sync(0xffffffffu, sl0, qb + e);
        float wt = __shfl_sync(0xffffffffu, wl0, qb + e);
        uint2 d = __ldg((const uint2*)(vh + (size_t)s * 32) + hl);
        float2 f0 = __half22float2(*(__half2*)&d.x);
        float2 f1 = __half22float2(*(__half2*)&d.y);
        a0 += wt * f0.x; a1 += wt * f0.y; a2 += wt * f1.x; a3 += wt * f1.y;
    }
#pragma unroll
    for (int e = 0; e < 8; e++) {
        int   s  = __shfl_sync(0xffffffffu, sl1, qb + e);
        float wt = __shfl_sync(0xffffffffu, wl1, qb + e);
        uint2 d = __ldg((const uint2*)(vh + (size_t)s * 32) + hl);
        float2 f0 = __half22float2(*(__half2*)&d.x);
        float2 f1 = __half22float2(*(__half2*)&d.y);
        a0 += wt * f0.x; a1 += wt * f0.y; a2 += wt * f1.x; a3 += wt * f1.y;
    }
    size_t o = (size_t)node * 32 + 4 * hl;
    float4 vv = *(const float4*)(v + o);     // T2
    float4 pp = *(const float4*)(p + o);     // T1
    float4 xx = *(const float4*)(x3 + o);    // layer-2 input
    int jc = 4 * hl;
    float4 u0 = *(const float4*)(W2 + jc);        // W2[0]
    float4 u1 = *(const float4*)(W2 + 32 + jc);   // W2[1]
    float4 u2 = *(const float4*)(W2 + 64 + jc);   // W2[2]
    float4 u3 = *(const float4*)(W2 + 96 + jc);   // W2[3]
    const float c3 = 1.f / 3.f;
    float t30 = (5.f * vv.x - 2.f * pp.x - a0) * c3;
    float t31 = (5.f * vv.y - 2.f * pp.y - a1) * c3;
    float t32 = (5.f * vv.z - 2.f * pp.z - a2) * c3;
    float t33 = (5.f * vv.w - 2.f * pp.w - a3) * c3;
    float val = xx.x * u0.x + xx.y * u0.y + xx.z * u0.z + xx.w * u0.w +
                pp.x * u1.x + pp.y * u1.y + pp.z * u1.z + pp.w * u1.w +
                vv.x * u2.x + vv.y * u2.y + vv.z * u2.z + vv.w * u2.w +
                t30 * u3.x + t31 * u3.y + t32 * u3.z + t33 * u3.w;
#pragma unroll
    for (int off = 4; off > 0; off >>= 1)
        val += __shfl_down_sync(0xffffffffu, val, off, 8);
    __shared__ float sh_s[32], sh_q[32];
    int wslot = (threadIdx.x >> 5) * 4 + qtr;
    if (hl == 0) {                   // b2 dropped: BN-invariant
        dXfPre[node] = val;
        sh_s[wslot] = val;
        sh_q[wslot] = val * val;
    }
    __syncthreads();
    if (threadIdx.x == 0) {
        float s = 0, q = 0;
        for (int i = 0; i < 32; i++) { s += sh_s[i]; q += sh_q[i]; }
        atomicAdd(&dAcc[96], (double)s);
        atomicAdd(&dAcc[97], (double)q);
    }
}

// ---------------- MLP head ----------------
__global__ void k_lin1(const float* __restrict__ W,
                       const float* __restrict__ g2, const float* __restrict__ be2) {
    __shared__ float sm[16 * 128];
    __shared__ float sSc, sSh;
    int c = threadIdx.x;
    if (c == 0) {
        double mean = dAcc[96] / (double)N2;
        double var  = dAcc[97] / (double)N2 - mean * mean;
        double sc = (double)g2[0] / sqrt(var + 1e-5);
        sSc = (float)sc;
        sSh = (float)((double)be2[0] - mean * sc);
    }
    __syncthreads();
    int jbase = blockIdx.x * 128;
    int rbase = blockIdx.y * 16;
    for (int i = c; i < 16 * 128; i += 256) {
        int r = i >> 7, j = i & 127, gj = jbase + j;
        float v = 0.f;
        if (gj < E2c) {
            v = dXfPre[(rbase + r) * E2c + gj] * sSc + sSh;
            v = v > 0.f ? v : SLOPE * v;
        }
        sm[i] = v;
    }
    __syncthreads();
    int jlim = E2c - jbase; if (jlim > 128) jlim = 128;
    float acc[16];
#pragma unroll
    for (int r = 0; r < 16; r++) acc[r] = 0.f;
    for (int j = 0; j < jlim; j++) {
        float w = __ldg(&W[(jbase + j) * 256 + c]);
#pragma unroll
        for (int r = 0; r < 16; r++) acc[r] += sm[r * 128 + j] * w;
    }
#pragma unroll
    for (int r = 0; r < 16; r++)
        atomicAdd(&dH1[(rbase + r) * 256 + c], acc[r]);
}

__global__ void k_bnrelu(float* __restrict__ H, const float* __restrict__ g,
                         const float* __restrict__ be, int C) {
    int c = threadIdx.x;
    if (c >= C) return;
    float s = 0, q = 0;
    for (int r = 0; r < Bq; r++) { float v = H[r * C + c]; s += v; q += v * v; }
    float mean = s / (float)Bq, var = q / (float)Bq - mean * mean;
    float sc = g[c] * rsqrtf(var + 1e-5f);
    float sh = be[c] - mean * sc;
    for (int r = 0; r < Bq; r++) {
        float v = H[r * C + c] * sc + sh;
        H[r * C + c] = fmaxf(v, 0.f);
    }
}

__global__ void k_lin2(const float* __restrict__ H1, const float* __restrict__ W,
                       const float* __restrict__ bias, float* __restrict__ H2) {
    __shared__ float row[256];
    int b = blockIdx.x, t = threadIdx.x;
    row[t] = H1[b * 256 + t];
    __syncthreads();
    if (t < 128) {
        float acc = bias[t];
        for (int j = 0; j < 256; j++)
            acc += row[j] * W[j * 128 + t];
        H2[b * 128 + t] = acc;
    }
}

__global__ void k_lin3(const float* __restrict__ H2, const float* __restrict__ W,
                       const float* __restrict__ bias, float* __restrict__ out) {
    int b = blockIdx.x, t = threadIdx.x;
    float p = H2[b * 128 + t] * W[t];
#pragma unroll
    for (int o = 16; o > 0; o >>= 1)
        p += __shfl_down_sync(0xffffffffu, p, o);
    __shared__ float sh[4];
    if ((t & 31) == 0) sh[t >> 5] = p;
    __syncthreads();
    if (t == 0) out[b] = sh[0] + sh[1] + sh[2] + sh[3] + bias[0];
}

// ---------------- launch ----------------
extern "C" void kernel_launch(void* const* d_in, const int* in_sizes, int n_in,
                              void* d_out, int out_size) {
    const float* x_s  = (const float*)d_in[0];
    const int*   ei1  = (const int*)d_in[1];
    const float* ew1  = (const float*)d_in[2];
    const int*   ei2  = (const int*)d_in[3];
    const float* ew2  = (const float*)d_in[4];
    const float* W0   = (const float*)d_in[5];
    const float* g0   = (const float*)d_in[7];
    const float* be0  = (const float*)d_in[8];
    const float* W1   = (const float*)d_in[9];
    const float* g1   = (const float*)d_in[11];
    const float* be1  = (const float*)d_in[12];
    const float* W2   = (const float*)d_in[13];
    const float* g2   = (const float*)d_in[15];
    const float* be2  = (const float*)d_in[16];
    const float* l1W  = (const float*)d_in[17];
    const float* l1b  = (const float*)d_in[18];
    const float* bn1g = (const float*)d_in[19];
    const float* bn1b = (const float*)d_in[20];
    const float* l2W  = (const float*)d_in[21];
    const float* l2b  = (const float*)d_in[22];
    const float* bn2g = (const float*)d_in[23];
    const float* bn2b = (const float*)d_in[24];
    const float* l3W  = (const float*)d_in[25];
    const float* l3b  = (const float*)d_in[26];

    const int* src1 = ei1;
    const int* src2 = ei2;

    float *pT1a, *pT2a, *pT3a, *pX2, *pT1, *pT2, *pOut, *pH1, *pH2;
    __half *pX2h, *pT1h, *pT2h, *pT3h, *pX3h;
    cudaGetSymbolAddress((void**)&pT1a, dT1a);
    cudaGetSymbolAddress((void**)&pT2a, dT2a);
    cudaGetSymbolAddress((void**)&pT3a, dT3a);
    cudaGetSymbolAddress((void**)&pX2, dX2);
    cudaGetSymbolAddress((void**)&pT1, dT1v);
    cudaGetSymbolAddress((void**)&pT2, dT2v);
    cudaGetSymbolAddress((void**)&pOut, dOutB);
    cudaGetSymbolAddress((void**)&pH1, dH1);
    cudaGetSymbolAddress((void**)&pH2, dH2);
    cudaGetSymbolAddress((void**)&pX2h, dX2h);
    cudaGetSymbolAddress((void**)&pT1h, dT1h);
    cudaGetSymbolAddress((void**)&pT2h, dT2h);
    cudaGetSymbolAddress((void**)&pT3h, dT3h);
    cudaGetSymbolAddress((void**)&pX3h, dX3h);

    const int NBV  = (N2 * 32) / 256;   // 35912
    const int NBV4 = (N2 * 8) / 256;    // 8978 (4-nodes-per-warp kernels)

    // ---- init (launch 1) ----
    k_init<<<65, 256>>>(l1b);

    // ---- layer 0 ----
    k_mv_scalar_s<<<NSB, 256>>>(x_s, x_s, pT1a, src1, ew1, 1.f, 0.f, 1.f);
    k_mv_scalar_s<<<NSB, 256>>>(pT1a, x_s, pT2a, src1, ew1, 3.f, -1.f, 0.5f);
    k_mv_scalar_s<<<NSB, 256>>>(pT2a, pT1a, pT3a, src1, ew1, 5.f, -2.f, 1.f / 3.f);
    k_stats0<<<562, 256>>>(x_s);
    k_prep0<<<1, 32>>>(W0, g0, be0);
    k_pool<<<NBV, 256>>>(x_s, W0);

    // ---- layer 1 (32ch Laguerre conv, 4 nodes/warp) ----
    k_mv_vec<<<NBV4, 256>>>(pX2, pX2h, pX2, pT1, pT1h, src2, ew2, 1.f, 0.f, 1.f, 1);
    k_mv_vec<<<NBV4, 256>>>(pT1, pT1h, pX2, pT2, pT2h, src2, ew2, 3.f, -1.f, 0.5f, 1);
    k_mv_vec<<<NBV4, 256>>>(pT2, pT2h, pT1, pT2, pT3h, src2, ew2, 5.f, -2.f, 1.f / 3.f, 0);
    k_outgemm_mma<<<(N2 + 127) / 128, 256>>>(pX2h, pT1h, pT2h, pT3h, W1, pOut);
    k_prep32<<<1, 32>>>(g1, be1);
    k_apply32<<<(N2 * 8) / 256, 256>>>(pOut, pX3h);    // in-place -> x3 (+fp16)

    // ---- layer 2 (32ch -> 1ch Laguerre conv, output fused, 4 nodes/warp) ----
    k_mv_vec<<<NBV4, 256>>>(pOut, pX3h, pOut, pT1, pT1h, src2, ew2, 1.f, 0.f, 1.f, 1);
    k_mv_vec<<<NBV4, 256>>>(pT1, pT1h, pOut, pT2, pT2h, src2, ew2, 3.f, -1.f, 0.5f, 1);
    k_mv_out2<<<NBV4, 256>>>(pT2, pT2h, pT1, pOut, src2, ew2, W2);

    // ---- MLP head (layer-2 BN fused into lin1) ----
    k_lin1<<<dim3(36, 4), 256>>>(l1W, g2, be2);
    k_bnrelu<<<1, 256>>>(pH1, bn1g, bn1b, 256);
    k_lin2<<<Bq, 256>>>(pH1, l2W, l2b, pH2);
    k_bnrelu<<<1, 128>>>(pH2, bn2g, bn2b, 128);
    k_lin3<<<Bq, 128>>>(pH2, l3W, l3b, (float*)d_out);
}